// round 12
// baseline (speedup 1.0000x reference)
#include <cuda_runtime.h>
#include <cuda_bf16.h>
#include <cstdint>

#define B_  2
#define S_  2048
#define D_  1024
#define H_  16
#define DH_ 64
#define MROWS (B_*S_)   // 4096
#define ISZ ((size_t)MROWS * D_)
#define WSZ ((size_t)D_ * D_)

// Scratch (allocation-free rule: __device__ globals)
__device__ __nv_bfloat16 g_inhi[3 * MROWS * D_];
__device__ __nv_bfloat16 g_inlo[3 * MROWS * D_];
__device__ __nv_bfloat16 g_qkvhi[3 * MROWS * D_];
__device__ __nv_bfloat16 g_qkvlo[3 * MROWS * D_];
__device__ __nv_bfloat16 g_chi[MROWS * D_];
__device__ __nv_bfloat16 g_clo[MROWS * D_];
__device__ __nv_bfloat16 g_whi[4][D_ * D_];
__device__ __nv_bfloat16 g_wlo[4][D_ * D_];

#define QSCALE (0.125f * 1.4426950408889634f)

// ---------------------------------------------------------------------------
// Helpers
// ---------------------------------------------------------------------------
__device__ __forceinline__ uint32_t smem_u32(const void* p) {
    uint32_t a;
    asm("{ .reg .u64 t; cvta.to.shared.u64 t, %1; cvt.u32.u64 %0, t; }"
        : "=r"(a) : "l"(p));
    return a;
}
__device__ __forceinline__ float ex2f(float x) {
    float r;
    asm("ex2.approx.f32 %0, %1;" : "=f"(r) : "f"(x));
    return r;
}
__device__ __forceinline__ void mma16816(float* c, const uint32_t* a, const uint32_t* b) {
    asm volatile(
        "mma.sync.aligned.m16n8k16.row.col.f32.bf16.bf16.f32 "
        "{%0,%1,%2,%3}, {%4,%5,%6,%7}, {%8,%9}, {%0,%1,%2,%3};"
        : "+f"(c[0]), "+f"(c[1]), "+f"(c[2]), "+f"(c[3])
        : "r"(a[0]), "r"(a[1]), "r"(a[2]), "r"(a[3]), "r"(b[0]), "r"(b[1]));
}

// Fast hi/lo split: hi = truncate-to-bf16 (prmt pack), lo = x - hi (exact),
// rounded to bf16 via packed cvt. 6 ops per pair.
__device__ __forceinline__ void split2(float x, float y, uint32_t& hi, uint32_t& lo) {
    const uint32_t xu = __float_as_uint(x), yu = __float_as_uint(y);
    uint32_t h;
    asm("prmt.b32 %0, %1, %2, 0x7632;" : "=r"(h) : "r"(xu), "r"(yu));
    const float lx = x - __uint_as_float(xu & 0xFFFF0000u);
    const float ly = y - __uint_as_float(yu & 0xFFFF0000u);
    uint32_t l;
    asm("cvt.rn.bf16x2.f32 %0, %1, %2;" : "=r"(l) : "f"(ly), "f"(lx));
    hi = h; lo = l;
}

__device__ __forceinline__ void cp16(uint32_t dst, const void* src) {
    asm volatile("cp.async.cg.shared.global [%0], [%1], 16;" :: "r"(dst), "l"(src));
}
__device__ __forceinline__ void cp_commit() {
    asm volatile("cp.async.commit_group;");
}
__device__ __forceinline__ void cp_wait_all() {
    asm volatile("cp.async.wait_group 0;");
}
__device__ __forceinline__ void ldsm4(uint32_t* r, uint32_t saddr) {
    asm volatile("ldmatrix.sync.aligned.m8n8.x4.shared.b16 {%0,%1,%2,%3}, [%4];"
        : "=r"(r[0]), "=r"(r[1]), "=r"(r[2]), "=r"(r[3]) : "r"(saddr));
}
__device__ __forceinline__ void ldsm4t(uint32_t* r, uint32_t saddr) {
    asm volatile("ldmatrix.sync.aligned.m8n8.x4.trans.shared.b16 {%0,%1,%2,%3}, [%4];"
        : "=r"(r[0]), "=r"(r[1]), "=r"(r[2]), "=r"(r[3]) : "r"(saddr));
}

// ---------------------------------------------------------------------------
// prep_w / prep_in
// ---------------------------------------------------------------------------
__global__ void prep_w(const float* __restrict__ W0, const float* __restrict__ W1,
                       const float* __restrict__ W2, const float* __restrict__ W3,
                       __nv_bfloat16* __restrict__ Whi, __nv_bfloat16* __restrict__ Wlo)
{
    __shared__ float t[32][33];
    const int z = blockIdx.z;
    const float* W = (z == 0) ? W0 : (z == 1) ? W1 : (z == 2) ? W2 : W3;
    const size_t zoff = (size_t)z * D_ * D_;
    const int n0 = blockIdx.x * 32, k0 = blockIdx.y * 32;
    const int tx = threadIdx.x, ty = threadIdx.y;
    #pragma unroll
    for (int j = 0; j < 32; j += 8)
        t[ty + j][tx] = W[(size_t)(k0 + ty + j) * D_ + n0 + tx];
    __syncthreads();
    #pragma unroll
    for (int j = 0; j < 32; j += 8) {
        float v = t[tx][ty + j];
        const uint32_t vu = __float_as_uint(v);
        const float hv = __uint_as_float(vu & 0xFFFF0000u);
        size_t o = zoff + (size_t)(n0 + ty + j) * D_ + k0 + tx;
        Whi[o] = __ushort_as_bfloat16((unsigned short)(vu >> 16));
        Wlo[o] = __float2bfloat16(v - hv);
    }
}

__global__ void prep_in(const float* __restrict__ q, const float* __restrict__ k,
                        const float* __restrict__ v,
                        __nv_bfloat16* __restrict__ hi, __nv_bfloat16* __restrict__ lo)
{
    const int z = blockIdx.y;
    const float* src = (z == 0) ? q : (z == 1) ? k : v;
    const size_t base4 = (size_t)z * (MROWS * D_ / 4);
    const size_t i = (size_t)blockIdx.x * 256 + threadIdx.x;
    float4 a = ((const float4*)src)[i];
    uint2 h2, l2;
    split2(a.x, a.y, h2.x, l2.x);
    split2(a.z, a.w, h2.y, l2.y);
    ((uint2*)hi)[base4 + i] = h2;
    ((uint2*)lo)[base4 + i] = l2;
}

// ---------------------------------------------------------------------------
// GEMM mainloop (R11): 2-stage cp.async + ldmatrix x4 pairs, pass-major order,
// A-fragment double-buffer. CTA 128x128, BK=32, 8 warps, 2 CTAs/SM.
// ---------------------------------------------------------------------------
#define GPADB 80
#define ARR_B (128 * GPADB)
#define STG_B (4 * ARR_B)
#define GEMM_SMEM (2 * STG_B)            // 81920 B

__device__ __forceinline__ void gemm_stage_load(
    uint32_t st, int m0, int n0, int k0, int r, int s0,
    const __nv_bfloat16* __restrict__ Ahi, const __nv_bfloat16* __restrict__ Alo,
    const __nv_bfloat16* __restrict__ Whi, const __nv_bfloat16* __restrict__ Wlo)
{
    #pragma unroll
    for (int i = 0; i < 2; i++) {
        const int seg = s0 + i;
        const uint32_t d = st + (uint32_t)(r * GPADB + seg * 16);
        const size_t ea = (size_t)(m0 + r) * D_ + k0 + seg * 8;
        const size_t eb = (size_t)(n0 + r) * D_ + k0 + seg * 8;
        cp16(d,             Ahi + ea);
        cp16(d + ARR_B,     Alo + ea);
        cp16(d + 2 * ARR_B, Whi + eb);
        cp16(d + 3 * ARR_B, Wlo + eb);
    }
}

__device__ __forceinline__ void gemm_mainloop(
    uint32_t sb, int tid, int m0, int n0,
    const __nv_bfloat16* __restrict__ Ahi, const __nv_bfloat16* __restrict__ Alo,
    const __nv_bfloat16* __restrict__ Whi, const __nv_bfloat16* __restrict__ Wlo,
    float acc[4][4][4])
{
    const int wid = tid >> 5, lid = tid & 31;
    const int wm = wid & 1, wn = wid >> 1;
    const int r = tid >> 1, s0 = (tid & 1) * 2;

    const uint32_t a_lane = (uint32_t)((wm * 64 + (lid & 15)) * GPADB + (lid >> 4) * 16);
    const uint32_t b_lane = (uint32_t)((wn * 32 + (lid & 7) + ((lid >> 4) << 3)) * GPADB
                                       + ((lid >> 3) & 1) * 16);

    gemm_stage_load(sb, m0, n0, 0, r, s0, Ahi, Alo, Whi, Wlo);
    cp_commit();
    cp_wait_all();
    __syncthreads();

    const int NCH = D_ / 32;
    for (int ch = 0; ch < NCH; ch++) {
        const int cs = ch & 1;
        if (ch + 1 < NCH) {
            gemm_stage_load(sb + (cs ^ 1) * STG_B, m0, n0, (ch + 1) * 32, r, s0,
                            Ahi, Alo, Whi, Wlo);
            cp_commit();
        }
        const uint32_t st = sb + cs * STG_B;
        #pragma unroll
        for (int ks = 0; ks < 2; ks++) {
            uint32_t bhf[4][2], blf[4][2];
            #pragma unroll
            for (int jg = 0; jg < 4; jg += 2) {
                const uint32_t ba = st + 2 * ARR_B + b_lane
                                  + (uint32_t)(jg * 8 * GPADB + ks * 32);
                uint32_t rr[4];
                ldsm4(rr, ba);
                bhf[jg][0] = rr[0]; bhf[jg][1] = rr[1];
                bhf[jg+1][0] = rr[2]; bhf[jg+1][1] = rr[3];
                ldsm4(rr, ba + ARR_B);
                blf[jg][0] = rr[0]; blf[jg][1] = rr[1];
                blf[jg+1][0] = rr[2]; blf[jg+1][1] = rr[3];
            }
            uint32_t ah2[2][4], al2[2][4];
            const uint32_t aa0 = st + a_lane + (uint32_t)(ks * 32);
            ldsm4(ah2[0], aa0);
            ldsm4(al2[0], aa0 + ARR_B);
            #pragma unroll
            for (int i = 0; i < 4; i++) {
                const int p = i & 1;
                if (i < 3) {
                    const uint32_t aa = st + a_lane
                                      + (uint32_t)((i + 1) * 16 * GPADB + ks * 32);
                    ldsm4(ah2[p ^ 1], aa);
                    ldsm4(al2[p ^ 1], aa + ARR_B);
                }
                #pragma unroll
                for (int j = 0; j < 4; j++) mma16816(acc[i][j], ah2[p], bhf[j]);
                #pragma unroll
                for (int j = 0; j < 4; j++) mma16816(acc[i][j], ah2[p], blf[j]);
                #pragma unroll
                for (int j = 0; j < 4; j++) mma16816(acc[i][j], al2[p], bhf[j]);
            }
        }
        if (ch + 1 < NCH) cp_wait_all();
        __syncthreads();
    }
}

// ---------------------------------------------------------------------------
// QKV GEMM (grid.z picks input/weight/bias); output pre-split hi/lo bf16.
// ---------------------------------------------------------------------------
__global__ void __launch_bounds__(256, 2)
gemm_qkv(const __nv_bfloat16* __restrict__ inhi, const __nv_bfloat16* __restrict__ inlo,
         const __nv_bfloat16* __restrict__ whi, const __nv_bfloat16* __restrict__ wlo,
         const float* __restrict__ bq, const float* __restrict__ bk,
         const float* __restrict__ bv,
         __nv_bfloat16* __restrict__ outhi, __nv_bfloat16* __restrict__ outlo)
{
    extern __shared__ uint32_t sg[];
    const uint32_t sb = smem_u32(sg);
    const int tid = threadIdx.x, wid = tid >> 5, lid = tid & 31;
    const int g = lid >> 2, tc = lid & 3;
    const int wm = wid & 1, wn = wid >> 1;
    const int m0 = blockIdx.y * 128, n0 = blockIdx.x * 128;
    const int z = blockIdx.z;

    const __nv_bfloat16* Ahi = inhi + (size_t)z * ISZ;
    const __nv_bfloat16* Alo = inlo + (size_t)z * ISZ;
    const __nv_bfloat16* Whi = whi + (size_t)z * WSZ;
    const __nv_bfloat16* Wlo = wlo + (size_t)z * WSZ;
    const float* bias = (z == 0) ? bq : (z == 1) ? bk : bv;
    const float scale = (z == 0) ? QSCALE : 1.0f;
    __nv_bfloat16* Ohi = outhi + (size_t)z * ISZ;
    __nv_bfloat16* Olo = outlo + (size_t)z * ISZ;

    float acc[4][4][4];
    #pragma unroll
    for (int i = 0; i < 4; i++)
        #pragma unroll
        for (int j = 0; j < 4; j++)
            #pragma unroll
            for (int q = 0; q < 4; q++) acc[i][j][q] = 0.0f;

    gemm_mainloop(sb, tid, m0, n0, Ahi, Alo, Whi, Wlo, acc);

    #pragma unroll
    for (int j = 0; j < 4; j++) {
        const int n = n0 + wn * 32 + j * 8 + tc * 2;
        const float2 b2 = *(const float2*)(bias + n);
        #pragma unroll
        for (int i = 0; i < 4; i++) {
            const int m = m0 + wm * 64 + i * 16 + g;
            uint32_t h0, l0, h1, l1;
            split2((acc[i][j][0] + b2.x) * scale, (acc[i][j][1] + b2.y) * scale, h0, l0);
            split2((acc[i][j][2] + b2.x) * scale, (acc[i][j][3] + b2.y) * scale, h1, l1);
            *(uint32_t*)(Ohi + (size_t)m * D_ + n) = h0;
            *(uint32_t*)(Olo + (size_t)m * D_ + n) = l0;
            *(uint32_t*)(Ohi + (size_t)(m + 8) * D_ + n) = h1;
            *(uint32_t*)(Olo + (size_t)(m + 8) * D_ + n) = l1;
        }
    }
}

// ---------------------------------------------------------------------------
// O projection GEMM: fp32 output + bias.
// ---------------------------------------------------------------------------
__global__ void __launch_bounds__(256, 2)
gemm_o(const __nv_bfloat16* __restrict__ Ahi, const __nv_bfloat16* __restrict__ Alo,
       const __nv_bfloat16* __restrict__ Whi, const __nv_bfloat16* __restrict__ Wlo,
       const float* __restrict__ bias, float* __restrict__ C)
{
    extern __shared__ uint32_t sg[];
    const uint32_t sb = smem_u32(sg);
    const int tid = threadIdx.x, wid = tid >> 5, lid = tid & 31;
    const int g = lid >> 2, tc = lid & 3;
    const int wm = wid & 1, wn = wid >> 1;
    const int m0 = blockIdx.y * 128, n0 = blockIdx.x * 128;

    float acc[4][4][4];
    #pragma unroll
    for (int i = 0; i < 4; i++)
        #pragma unroll
        for (int j = 0; j < 4; j++)
            #pragma unroll
            for (int q = 0; q < 4; q++) acc[i][j][q] = 0.0f;

    gemm_mainloop(sb, tid, m0, n0, Ahi, Alo, Whi, Wlo, acc);

    #pragma unroll
    for (int j = 0; j < 4; j++) {
        const int n = n0 + wn * 32 + j * 8 + tc * 2;
        const float2 b2 = *(const float2*)(bias + n);
        #pragma unroll
        for (int i = 0; i < 4; i++) {
            const int m = m0 + wm * 64 + i * 16 + g;
            float2 o0, o1;
            o0.x = acc[i][j][0] + b2.x; o0.y = acc[i][j][1] + b2.y;
            o1.x = acc[i][j][2] + b2.x; o1.y = acc[i][j][3] + b2.y;
            *(float2*)(C + (size_t)m * D_ + n) = o0;
            *(float2*)(C + (size_t)(m + 8) * D_ + n) = o1;
        }
    }
}

// ---------------------------------------------------------------------------
// HMMA flash attention: kv tile = 128, double-buffered stages. Softmax ex2 +
// P-split + l-sum fused into the PV pipeline (MUFU overlaps tensor); ls shfl
// deferred to after PV; causal PV k-step skip. 1 CTA/SM.
// ---------------------------------------------------------------------------
#define FROWB 144
#define KARRB (128 * FROWB)              // 18432
#define FSTGB (4 * KARRB)                // 73728
#define FAH_SMEM (2 * FSTGB)             // 147456

__device__ __forceinline__ void fa_stage_load(
    uint32_t stb, size_t base, int k0, int tid,
    const __nv_bfloat16* __restrict__ Khi, const __nv_bfloat16* __restrict__ Klo,
    const __nv_bfloat16* __restrict__ Vhi, const __nv_bfloat16* __restrict__ Vlo)
{
    const int arr = tid >> 6, row0 = tid & 63;
    const __nv_bfloat16* src = (arr == 0) ? Khi : (arr == 1) ? Klo
                              : (arr == 2) ? Vhi : Vlo;
    #pragma unroll
    for (int rr = 0; rr < 2; rr++) {
        const int row = row0 + rr * 64;
        const __nv_bfloat16* p = src + base + (size_t)(k0 + row) * D_;
        const uint32_t d = stb + arr * KARRB + row * FROWB;
        #pragma unroll
        for (int seg = 0; seg < 8; seg++)
            cp16(d + seg * 16, p + seg * 8);
    }
}

#define LOADK(ks_, jg_, p_) do {                                               \
    _Pragma("unroll")                                                          \
    for (int t2 = 0; t2 < 4; t2++) {                                           \
        const uint32_t ba = stb + kb4                                          \
            + (uint32_t)(((jg_) + 2 * t2) * 8 * FROWB + (ks_) * 32);           \
        uint32_t rr[4];                                                        \
        ldsm4(rr, ba);                                                         \
        kh2[p_][2*t2][0] = rr[0]; kh2[p_][2*t2][1] = rr[1];                    \
        kh2[p_][2*t2+1][0] = rr[2]; kh2[p_][2*t2+1][1] = rr[3];                \
        ldsm4(rr, ba + KARRB);                                                 \
        kl2[p_][2*t2][0] = rr[0]; kl2[p_][2*t2][1] = rr[1];                    \
        kl2[p_][2*t2+1][0] = rr[2]; kl2[p_][2*t2+1][1] = rr[3];                \
    }                                                                          \
} while (0)

#define LOADV(ks_, p_) do {                                                    \
    _Pragma("unroll")                                                          \
    for (int t2 = 0; t2 < 4; t2++) {                                           \
        const uint32_t va = stb + 2 * KARRB + vb4                              \
            + (uint32_t)((ks_) * 16 * FROWB + 2 * t2 * 16);                    \
        uint32_t rr[4];                                                        \
        ldsm4t(rr, va);                                                        \
        vh2[p_][2*t2][0] = rr[0]; vh2[p_][2*t2][1] = rr[1];                    \
        vh2[p_][2*t2+1][0] = rr[2]; vh2[p_][2*t2+1][1] = rr[3];                \
        ldsm4t(rr, va + KARRB);                                                \
        vl2[p_][2*t2][0] = rr[0]; vl2[p_][2*t2][1] = rr[1];                    \
        vl2[p_][2*t2+1][0] = rr[2]; vl2[p_][2*t2+1][1] = rr[3];                \
    }                                                                          \
} while (0)

// ex2 + l-accumulate + hi/lo split for one PV k-step (8 P values)
#define PEXPSPLIT(ks_, p_) do {                                                \
    const float e0 = ex2f(sacc[2*(ks_)][0]   - mn0);                           \
    const float e1 = ex2f(sacc[2*(ks_)][1]   - mn0);                           \
    const float e2 = ex2f(sacc[2*(ks_)][2]   - mn1);                           \
    const float e3 = ex2f(sacc[2*(ks_)][3]   - mn1);                           \
    const float e4 = ex2f(sacc[2*(ks_)+1][0] - mn0);                           \
    const float e5 = ex2f(sacc[2*(ks_)+1][1] - mn0);                           \
    const float e6 = ex2f(sacc[2*(ks_)+1][2] - mn1);                           \
    const float e7 = ex2f(sacc[2*(ks_)+1][3] - mn1);                           \
    ls0 += (e0 + e1) + (e4 + e5);                                              \
    ls1 += (e2 + e3) + (e6 + e7);                                              \
    split2(e0, e1, pah2[p_][0], pal2[p_][0]);                                  \
    split2(e2, e3, pah2[p_][1], pal2[p_][1]);                                  \
    split2(e4, e5, pah2[p_][2], pal2[p_][2]);                                  \
    split2(e6, e7, pah2[p_][3], pal2[p_][3]);                                  \
} while (0)

__global__ void __launch_bounds__(256, 1)
flash_hmma(const __nv_bfloat16* __restrict__ Qhi, const __nv_bfloat16* __restrict__ Qlo,
           const __nv_bfloat16* __restrict__ Khi, const __nv_bfloat16* __restrict__ Klo,
           const __nv_bfloat16* __restrict__ Vhi, const __nv_bfloat16* __restrict__ Vlo,
           __nv_bfloat16* __restrict__ chi, __nv_bfloat16* __restrict__ clo)
{
    extern __shared__ uint32_t su[];
    const uint32_t sb = smem_u32(su);
    char* sc = (char*)su;

    const int tid = threadIdx.x, wid = tid >> 5, lid = tid & 31;
    const int g = lid >> 2, tc = lid & 3;
    const int bh = blockIdx.y;
    const int bx = (int)gridDim.x - 1 - (int)blockIdx.x;   // heavy tiles first
    const int b = bh / H_, h = bh % H_;
    const int q0 = bx * 128;
    const size_t base = (size_t)b * S_ * D_ + (size_t)h * DH_;
    const int wrow = q0 + wid * 16;
    const int ktiles = bx + 1;

    fa_stage_load(sb, base, 0, tid, Khi, Klo, Vhi, Vlo);
    cp_commit();

    #pragma unroll
    for (int it = 0; it < 4; it++) {
        const int idx = tid + it * 256;
        const int row = idx >> 3, seg = idx & 7;
        const size_t e = base + (size_t)(q0 + row) * D_ + seg * 8;
        *(uint4*)(sc + FSTGB + row * FROWB + seg * 16)         = *(const uint4*)(Qhi + e);
        *(uint4*)(sc + FSTGB + KARRB + row * FROWB + seg * 16) = *(const uint4*)(Qlo + e);
    }
    __syncthreads();

    uint32_t qh[4][4], ql[4][4];
    {
        const uint32_t aa0 = sb + FSTGB
                           + (uint32_t)((wid * 16 + (lid & 15)) * FROWB + (lid >> 4) * 16);
        #pragma unroll
        for (int ks = 0; ks < 4; ks++) {
            ldsm4(qh[ks], aa0 + ks * 32);
            ldsm4(ql[ks], aa0 + KARRB + ks * 32);
        }
    }

    float oacc[8][4];
    #pragma unroll
    for (int j = 0; j < 8; j++)
        #pragma unroll
        for (int q = 0; q < 4; q++) oacc[j][q] = 0.0f;
    float m0r = -1e30f, m1r = -1e30f, l0r = 0.0f, l1r = 0.0f;

    const uint32_t kb4 = (uint32_t)(((lid & 7) + ((lid >> 4) << 3)) * FROWB
                                    + ((lid >> 3) & 1) * 16);
    const uint32_t vb4 = (uint32_t)((lid & 15) * FROWB + ((lid >> 4) & 1) * 16);

    for (int kt = 0; kt < ktiles; kt++) {
        const int k0 = kt * 128;
        cp_wait_all();
        __syncthreads();
        if (kt + 1 < ktiles) {
            fa_stage_load(sb + ((kt + 1) & 1) * FSTGB, base, k0 + 128, tid,
                          Khi, Klo, Vhi, Vlo);
            cp_commit();
        }

        const uint32_t stb = sb + (kt & 1) * FSTGB;

        // ---- S = Q @ K^T ----
        float sacc[16][4];
        #pragma unroll
        for (int j = 0; j < 16; j++)
            #pragma unroll
            for (int q = 0; q < 4; q++) sacc[j][q] = 0.0f;

        {
            uint32_t kh2[2][8][2], kl2[2][8][2];
            LOADK(0, 0, 0);
            #pragma unroll
            for (int st = 0; st < 8; st++) {
                const int ks = st >> 1, jg = (st & 1) * 8, p = st & 1;
                if (st < 7) {
                    const int ks2 = (st + 1) >> 1, jg2 = ((st + 1) & 1) * 8;
                    LOADK(ks2, jg2, p ^ 1);
                }
                #pragma unroll
                for (int t = 0; t < 8; t++) mma16816(sacc[jg + t], qh[ks], kh2[p][t]);
                #pragma unroll
                for (int t = 0; t < 8; t++) mma16816(sacc[jg + t], qh[ks], kl2[p][t]);
                #pragma unroll
                for (int t = 0; t < 8; t++) mma16816(sacc[jg + t], ql[ks], kh2[p][t]);
            }
        }

        // ---- causal mask (diagonal tile only) ----
        const bool diag = (k0 + 127 > wrow);
        if (diag) {
            #pragma unroll
            for (int jn = 0; jn < 16; jn++) {
                const int c0 = k0 + jn * 8 + 2 * tc;
                const int r0g = wrow + g;
                if (c0     > r0g)     sacc[jn][0] = -1e30f;
                if (c0 + 1 > r0g)     sacc[jn][1] = -1e30f;
                if (c0     > r0g + 8) sacc[jn][2] = -1e30f;
                if (c0 + 1 > r0g + 8) sacc[jn][3] = -1e30f;
            }
        }

        // ---- row max + alpha (only shfl on critical path) ----
        float mt0 = -1e30f, mt1 = -1e30f;
        #pragma unroll
        for (int jn = 0; jn < 16; jn += 2) {
            float u = fmaxf(fmaxf(sacc[jn][0], sacc[jn][1]),
                            fmaxf(sacc[jn+1][0], sacc[jn+1][1]));
            float v = fmaxf(fmaxf(sacc[jn][2], sacc[jn][3]),
                            fmaxf(sacc[jn+1][2], sacc[jn+1][3]));
            mt0 = fmaxf(mt0, u);
            mt1 = fmaxf(mt1, v);
        }
        mt0 = fmaxf(mt0, __shfl_xor_sync(0xffffffffu, mt0, 1));
        mt0 = fmaxf(mt0, __shfl_xor_sync(0xffffffffu, mt0, 2));
        mt1 = fmaxf(mt1, __shfl_xor_sync(0xffffffffu, mt1, 1));
        mt1 = fmaxf(mt1, __shfl_xor_sync(0xffffffffu, mt1, 2));

        const float mn0 = fmaxf(m0r, mt0), mn1 = fmaxf(m1r, mt1);
        const float al0 = ex2f(m0r - mn0), al1 = ex2f(m1r - mn1);
        m0r = mn0; m1r = mn1;

        #pragma unroll
        for (int jn = 0; jn < 8; jn++) {
            oacc[jn][0] *= al0; oacc[jn][1] *= al0;
            oacc[jn][2] *= al1; oacc[jn][3] *= al1;
        }

        // ---- PV pipeline: ex2+split+lsum fused with MMAs; causal ks skip ----
        {
            float ls0 = 0.0f, ls1 = 0.0f;
            int nks = 8;
            if (diag) nks = ((wrow + 15 - k0) >> 4) + 1;

            uint32_t vh2[2][8][2], vl2[2][8][2];
            uint32_t pah2[2][4], pal2[2][4];
            LOADV(0, 0);
            PEXPSPLIT(0, 0);
            #pragma unroll
            for (int ks = 0; ks < 8; ks++) {
                if (ks >= nks) break;
                const int p = ks & 1;
                if (ks + 1 < nks) {
                    LOADV(ks + 1, p ^ 1);
                    PEXPSPLIT(ks + 1, p ^ 1);
                }
                #pragma unroll
                for (int t = 0; t < 8; t++) mma16816(oacc[t], pah2[p], vh2[p][t]);
                #pragma unroll
                for (int t = 0; t < 8; t++) mma16816(oacc[t], pah2[p], vl2[p][t]);
                #pragma unroll
                for (int t = 0; t < 8; t++) mma16816(oacc[t], pal2[p], vh2[p][t]);
            }

            // deferred l reduction (off the PV critical path)
            ls0 += __shfl_xor_sync(0xffffffffu, ls0, 1);
            ls0 += __shfl_xor_sync(0xffffffffu, ls0, 2);
            ls1 += __shfl_xor_sync(0xffffffffu, ls1, 1);
            ls1 += __shfl_xor_sync(0xffffffffu, ls1, 2);
            l0r = l0r * al0 + ls0;
            l1r = l1r * al1 + ls1;
        }
    }

    const float inv0 = 1.0f / l0r, inv1 = 1.0f / l1r;
    const int row0 = q0 + wid * 16 + g;
    #pragma unroll
    for (int jn = 0; jn < 8; jn++) {
        const int c = jn * 8 + 2 * tc;
        uint32_t h0, l0, h1, l1;
        split2(oacc[jn][0] * inv0, oacc[jn][1] * inv0, h0, l0);
        split2(oacc[jn][2] * inv1, oacc[jn][3] * inv1, h1, l1);
        const size_t e0 = base + (size_t)row0 * D_ + c;
        const size_t e1 = base + (size_t)(row0 + 8) * D_ + c;
        *(uint32_t*)(chi + e0) = h0;
        *(uint32_t*)(clo + e0) = l0;
        *(uint32_t*)(chi + e1) = h1;
        *(uint32_t*)(clo + e1) = l1;
    }
}

// ---------------------------------------------------------------------------
// Launch
// ---------------------------------------------------------------------------
extern "C" void kernel_launch(void* const* d_in, const int* in_sizes, int n_in,
                              void* d_out, int out_size)
{
    const float* query = (const float*)d_in[0];
    const float* key   = (const float*)d_in[1];
    const float* value = (const float*)d_in[2];
    const float* Wq    = (const float*)d_in[4];
    const float* bq    = (const float*)d_in[5];
    const float* Wk    = (const float*)d_in[6];
    const float* bk    = (const float*)d_in[7];
    const float* Wv    = (const float*)d_in[8];
    const float* bv    = (const float*)d_in[9];
    const float* Wo    = (const float*)d_in[10];
    const float* bo    = (const float*)d_in[11];
    float* out = (float*)d_out;

    __nv_bfloat16 *inhi, *inlo, *qkvhi, *qkvlo, *chi, *clo, *whi, *wlo;
    cudaGetSymbolAddress((void**)&inhi, g_inhi);
    cudaGetSymbolAddress((void**)&inlo, g_inlo);
    cudaGetSymbolAddress((void**)&qkvhi, g_qkvhi);
    cudaGetSymbolAddress((void**)&qkvlo, g_qkvlo);
    cudaGetSymbolAddress((void**)&chi, g_chi);
    cudaGetSymbolAddress((void**)&clo, g_clo);
    cudaGetSymbolAddress((void**)&whi, g_whi);
    cudaGetSymbolAddress((void**)&wlo, g_wlo);

    cudaFuncSetAttribute(gemm_qkv, cudaFuncAttributeMaxDynamicSharedMemorySize, GEMM_SMEM);
    cudaFuncSetAttribute(gemm_o,   cudaFuncAttributeMaxDynamicSharedMemorySize, GEMM_SMEM);
    cudaFuncSetAttribute(flash_hmma, cudaFuncAttributeMaxDynamicSharedMemorySize, FAH_SMEM);

    prep_w<<<dim3(32, 32, 4), dim3(32, 8)>>>(Wq, Wk, Wv, Wo, whi, wlo);
    prep_in<<<dim3(MROWS * D_ / 4 / 256, 3), 256>>>(query, key, value, inhi, inlo);

    gemm_qkv<<<dim3(D_ / 128, MROWS / 128, 3), 256, GEMM_SMEM>>>(
        inhi, inlo, whi, wlo, bq, bk, bv, qkvhi, qkvlo);

    flash_hmma<<<dim3(S_ / 128, B_ * H_), 256, FAH_SMEM>>>(
        qkvhi, qkvlo,
        qkvhi + ISZ, qkvlo + ISZ,
        qkvhi + 2 * ISZ, qkvlo + 2 * ISZ,
        chi, clo);

    gemm_o<<<dim3(D_ / 128, MROWS / 128), 256, GEMM_SMEM>>>(
        chi, clo, whi + 3 * WSZ, wlo + 3 * WSZ, bo, out);
}

// round 13
// speedup vs baseline: 1.4366x; 1.4366x over previous
#include <cuda_runtime.h>
#include <cuda_bf16.h>
#include <cuda_fp16.h>
#include <cstdint>

#define B_  2
#define S_  2048
#define D_  1024
#define H_  16
#define DH_ 64
#define MROWS (B_*S_)   // 4096
#define ISZ ((size_t)MROWS * D_)
#define WSZ ((size_t)D_ * D_)

// Scratch (allocation-free rule: __device__ globals). 16-bit payloads are fp16.
__device__ __half g_inhi[3 * MROWS * D_];
__device__ __half g_inlo[3 * MROWS * D_];
__device__ __half g_qkvhi[3 * MROWS * D_];
__device__ __half g_qkvlo[3 * MROWS * D_];
__device__ __half g_chi[MROWS * D_];
__device__ __half g_clo[MROWS * D_];
__device__ __half g_whi[4][D_ * D_];

#define QSCALE (0.125f * 1.4426950408889634f)

// ---------------------------------------------------------------------------
// Helpers
// ---------------------------------------------------------------------------
__device__ __forceinline__ uint32_t smem_u32(const void* p) {
    uint32_t a;
    asm("{ .reg .u64 t; cvta.to.shared.u64 t, %1; cvt.u32.u64 %0, t; }"
        : "=r"(a) : "l"(p));
    return a;
}
__device__ __forceinline__ float ex2f(float x) {
    float r;
    asm("ex2.approx.f32 %0, %1;" : "=f"(r) : "f"(x));
    return r;
}
// fp16 MMA: D(16x8 fp32) += A(16x16 fp16) @ B(16x8 fp16)
__device__ __forceinline__ void mma16816(float* c, const uint32_t* a, const uint32_t* b) {
    asm volatile(
        "mma.sync.aligned.m16n8k16.row.col.f32.f16.f16.f32 "
        "{%0,%1,%2,%3}, {%4,%5,%6,%7}, {%8,%9}, {%0,%1,%2,%3};"
        : "+f"(c[0]), "+f"(c[1]), "+f"(c[2]), "+f"(c[3])
        : "r"(a[0]), "r"(a[1]), "r"(a[2]), "r"(a[3]), "r"(b[0]), "r"(b[1]));
}

// fp16 hi/lo split (RN): hi = rn16(x), lo = rn16(x - hi). ~7 ops per pair.
__device__ __forceinline__ void split2h(float x, float y, uint32_t& hi, uint32_t& lo) {
    uint32_t h;
    asm("cvt.rn.f16x2.f32 %0, %1, %2;" : "=r"(h) : "f"(y), "f"(x));
    const __half2 hh = *reinterpret_cast<const __half2*>(&h);
    const float hx = __low2float(hh), hy = __high2float(hh);
    uint32_t l;
    asm("cvt.rn.f16x2.f32 %0, %1, %2;" : "=r"(l) : "f"(y - hy), "f"(x - hx));
    hi = h; lo = l;
}

__device__ __forceinline__ void cp16(uint32_t dst, const void* src) {
    asm volatile("cp.async.cg.shared.global [%0], [%1], 16;" :: "r"(dst), "l"(src));
}
__device__ __forceinline__ void cp_commit() {
    asm volatile("cp.async.commit_group;");
}
__device__ __forceinline__ void cp_wait_all() {
    asm volatile("cp.async.wait_group 0;");
}
__device__ __forceinline__ void ldsm4(uint32_t* r, uint32_t saddr) {
    asm volatile("ldmatrix.sync.aligned.m8n8.x4.shared.b16 {%0,%1,%2,%3}, [%4];"
        : "=r"(r[0]), "=r"(r[1]), "=r"(r[2]), "=r"(r[3]) : "r"(saddr));
}
__device__ __forceinline__ void ldsm4t(uint32_t* r, uint32_t saddr) {
    asm volatile("ldmatrix.sync.aligned.m8n8.x4.trans.shared.b16 {%0,%1,%2,%3}, [%4];"
        : "=r"(r[0]), "=r"(r[1]), "=r"(r[2]), "=r"(r[3]) : "r"(saddr));
}

// ---------------------------------------------------------------------------
// prep_w: W[k][n] fp32 -> Whi[n][k] fp16 RN (B operand: hi only)
// ---------------------------------------------------------------------------
__global__ void prep_w(const float* __restrict__ W0, const float* __restrict__ W1,
                       const float* __restrict__ W2, const float* __restrict__ W3,
                       __half* __restrict__ Whi)
{
    __shared__ float t[32][33];
    const int z = blockIdx.z;
    const float* W = (z == 0) ? W0 : (z == 1) ? W1 : (z == 2) ? W2 : W3;
    const size_t zoff = (size_t)z * D_ * D_;
    const int n0 = blockIdx.x * 32, k0 = blockIdx.y * 32;
    const int tx = threadIdx.x, ty = threadIdx.y;
    #pragma unroll
    for (int j = 0; j < 32; j += 8)
        t[ty + j][tx] = W[(size_t)(k0 + ty + j) * D_ + n0 + tx];
    __syncthreads();
    #pragma unroll
    for (int j = 0; j < 32; j += 8) {
        float v = t[tx][ty + j];
        Whi[zoff + (size_t)(n0 + ty + j) * D_ + k0 + tx] = __float2half_rn(v);
    }
}

// ---------------------------------------------------------------------------
// prep_in: fp32 [M,K] -> fp16 hi/lo (A operand: split), 3 inputs per launch
// ---------------------------------------------------------------------------
__global__ void prep_in(const float* __restrict__ q, const float* __restrict__ k,
                        const float* __restrict__ v,
                        __half* __restrict__ hi, __half* __restrict__ lo)
{
    const int z = blockIdx.y;
    const float* src = (z == 0) ? q : (z == 1) ? k : v;
    const size_t base4 = (size_t)z * (MROWS * D_ / 4);
    const size_t i = (size_t)blockIdx.x * 256 + threadIdx.x;
    float4 a = ((const float4*)src)[i];
    uint2 h2, l2;
    split2h(a.x, a.y, h2.x, l2.x);
    split2h(a.z, a.w, h2.y, l2.y);
    ((uint2*)hi)[base4 + i] = h2;
    ((uint2*)lo)[base4 + i] = l2;
}

// ---------------------------------------------------------------------------
// GEMM mainloop: 2-stage cp.async + ldmatrix, fp16 2-MMA scheme.
// C = (Ahi + Alo) @ Whi^T. Stage = Ahi|Alo|Whi (3 arrays, 80B rows).
// CTA 128x128, BK=32, 8 warps (2m x 4n), 2 CTAs/SM.
// ---------------------------------------------------------------------------
#define GPADB 80
#define ARR_B (128 * GPADB)
#define STG_B (3 * ARR_B)
#define GEMM_SMEM (2 * STG_B)            // 61440 B

__device__ __forceinline__ void gemm_stage_load(
    uint32_t st, int m0, int n0, int k0, int r, int s0,
    const __half* __restrict__ Ahi, const __half* __restrict__ Alo,
    const __half* __restrict__ Whi)
{
    #pragma unroll
    for (int i = 0; i < 2; i++) {
        const int seg = s0 + i;
        const uint32_t d = st + (uint32_t)(r * GPADB + seg * 16);
        const size_t ea = (size_t)(m0 + r) * D_ + k0 + seg * 8;
        const size_t eb = (size_t)(n0 + r) * D_ + k0 + seg * 8;
        cp16(d,             Ahi + ea);
        cp16(d + ARR_B,     Alo + ea);
        cp16(d + 2 * ARR_B, Whi + eb);
    }
}

__device__ __forceinline__ void gemm_mainloop(
    uint32_t sb, int tid, int m0, int n0,
    const __half* __restrict__ Ahi, const __half* __restrict__ Alo,
    const __half* __restrict__ Whi,
    float acc[4][4][4])
{
    const int wid = tid >> 5, lid = tid & 31;
    const int wm = wid & 1, wn = wid >> 1;
    const int r = tid >> 1, s0 = (tid & 1) * 2;

    const uint32_t a_lane = (uint32_t)((wm * 64 + (lid & 15)) * GPADB + (lid >> 4) * 16);
    const uint32_t b_lane = (uint32_t)((wn * 32 + (lid & 7) + ((lid >> 4) << 3)) * GPADB
                                       + ((lid >> 3) & 1) * 16);

    gemm_stage_load(sb, m0, n0, 0, r, s0, Ahi, Alo, Whi);
    cp_commit();
    cp_wait_all();
    __syncthreads();

    const int NCH = D_ / 32;
    for (int ch = 0; ch < NCH; ch++) {
        const int cs = ch & 1;
        if (ch + 1 < NCH) {
            gemm_stage_load(sb + (cs ^ 1) * STG_B, m0, n0, (ch + 1) * 32, r, s0,
                            Ahi, Alo, Whi);
            cp_commit();
        }
        const uint32_t st = sb + cs * STG_B;
        #pragma unroll
        for (int ks = 0; ks < 2; ks++) {
            uint32_t bhf[4][2];
            #pragma unroll
            for (int jg = 0; jg < 4; jg += 2) {
                const uint32_t ba = st + 2 * ARR_B + b_lane
                                  + (uint32_t)(jg * 8 * GPADB + ks * 32);
                uint32_t rr[4];
                ldsm4(rr, ba);
                bhf[jg][0] = rr[0]; bhf[jg][1] = rr[1];
                bhf[jg+1][0] = rr[2]; bhf[jg+1][1] = rr[3];
            }
            // A fragments double-buffered across i
            uint32_t ah2[2][4], al2[2][4];
            const uint32_t aa0 = st + a_lane + (uint32_t)(ks * 32);
            ldsm4(ah2[0], aa0);
            ldsm4(al2[0], aa0 + ARR_B);
            #pragma unroll
            for (int i = 0; i < 4; i++) {
                const int p = i & 1;
                if (i < 3) {
                    const uint32_t aa = st + a_lane
                                      + (uint32_t)((i + 1) * 16 * GPADB + ks * 32);
                    ldsm4(ah2[p ^ 1], aa);
                    ldsm4(al2[p ^ 1], aa + ARR_B);
                }
                #pragma unroll
                for (int j = 0; j < 4; j++) mma16816(acc[i][j], ah2[p], bhf[j]);
                #pragma unroll
                for (int j = 0; j < 4; j++) mma16816(acc[i][j], al2[p], bhf[j]);
            }
        }
        if (ch + 1 < NCH) cp_wait_all();
        __syncthreads();
    }
}

// ---------------------------------------------------------------------------
// QKV GEMM (grid.z picks input/weight/bias); output pre-split fp16 hi/lo.
// ---------------------------------------------------------------------------
__global__ void __launch_bounds__(256, 2)
gemm_qkv(const __half* __restrict__ inhi, const __half* __restrict__ inlo,
         const __half* __restrict__ whi,
         const float* __restrict__ bq, const float* __restrict__ bk,
         const float* __restrict__ bv,
         __half* __restrict__ outhi, __half* __restrict__ outlo)
{
    extern __shared__ uint32_t sg[];
    const uint32_t sb = smem_u32(sg);
    const int tid = threadIdx.x, wid = tid >> 5, lid = tid & 31;
    const int g = lid >> 2, tc = lid & 3;
    const int wm = wid & 1, wn = wid >> 1;
    const int m0 = blockIdx.y * 128, n0 = blockIdx.x * 128;
    const int z = blockIdx.z;

    const __half* Ahi = inhi + (size_t)z * ISZ;
    const __half* Alo = inlo + (size_t)z * ISZ;
    const __half* Whi = whi + (size_t)z * WSZ;
    const float* bias = (z == 0) ? bq : (z == 1) ? bk : bv;
    const float scale = (z == 0) ? QSCALE : 1.0f;
    __half* Ohi = outhi + (size_t)z * ISZ;
    __half* Olo = outlo + (size_t)z * ISZ;

    float acc[4][4][4];
    #pragma unroll
    for (int i = 0; i < 4; i++)
        #pragma unroll
        for (int j = 0; j < 4; j++)
            #pragma unroll
            for (int q = 0; q < 4; q++) acc[i][j][q] = 0.0f;

    gemm_mainloop(sb, tid, m0, n0, Ahi, Alo, Whi, acc);

    #pragma unroll
    for (int j = 0; j < 4; j++) {
        const int n = n0 + wn * 32 + j * 8 + tc * 2;
        const float2 b2 = *(const float2*)(bias + n);
        #pragma unroll
        for (int i = 0; i < 4; i++) {
            const int m = m0 + wm * 64 + i * 16 + g;
            uint32_t h0, l0, h1, l1;
            split2h((acc[i][j][0] + b2.x) * scale, (acc[i][j][1] + b2.y) * scale, h0, l0);
            split2h((acc[i][j][2] + b2.x) * scale, (acc[i][j][3] + b2.y) * scale, h1, l1);
            *(uint32_t*)(Ohi + (size_t)m * D_ + n) = h0;
            *(uint32_t*)(Olo + (size_t)m * D_ + n) = l0;
            *(uint32_t*)(Ohi + (size_t)(m + 8) * D_ + n) = h1;
            *(uint32_t*)(Olo + (size_t)(m + 8) * D_ + n) = l1;
        }
    }
}

// ---------------------------------------------------------------------------
// O projection GEMM: fp32 output + bias.
// ---------------------------------------------------------------------------
__global__ void __launch_bounds__(256, 2)
gemm_o(const __half* __restrict__ Ahi, const __half* __restrict__ Alo,
       const __half* __restrict__ Whi,
       const float* __restrict__ bias, float* __restrict__ C)
{
    extern __shared__ uint32_t sg[];
    const uint32_t sb = smem_u32(sg);
    const int tid = threadIdx.x, wid = tid >> 5, lid = tid & 31;
    const int g = lid >> 2, tc = lid & 3;
    const int wm = wid & 1, wn = wid >> 1;
    const int m0 = blockIdx.y * 128, n0 = blockIdx.x * 128;

    float acc[4][4][4];
    #pragma unroll
    for (int i = 0; i < 4; i++)
        #pragma unroll
        for (int j = 0; j < 4; j++)
            #pragma unroll
            for (int q = 0; q < 4; q++) acc[i][j][q] = 0.0f;

    gemm_mainloop(sb, tid, m0, n0, Ahi, Alo, Whi, acc);

    #pragma unroll
    for (int j = 0; j < 4; j++) {
        const int n = n0 + wn * 32 + j * 8 + tc * 2;
        const float2 b2 = *(const float2*)(bias + n);
        #pragma unroll
        for (int i = 0; i < 4; i++) {
            const int m = m0 + wm * 64 + i * 16 + g;
            float2 o0, o1;
            o0.x = acc[i][j][0] + b2.x; o0.y = acc[i][j][1] + b2.y;
            o1.x = acc[i][j][2] + b2.x; o1.y = acc[i][j][3] + b2.y;
            *(float2*)(C + (size_t)m * D_ + n) = o0;
            *(float2*)(C + (size_t)(m + 8) * D_ + n) = o1;
        }
    }
}

// ---------------------------------------------------------------------------
// HMMA flash attention (R11 structure, fp16 2-MMA): kv tile = 128,
// K/V hi-only (stage = Khi|Vhi), Q fp16 hi/lo, P split in regs.
// smem: 2 stages x 36864 = 73728 B; Q stages through buffer 1. 1 CTA/SM.
// ---------------------------------------------------------------------------
#define FROWB 144
#define KARRB (128 * FROWB)              // 18432
#define FSTGB (2 * KARRB)                // 36864
#define FAH_SMEM (2 * FSTGB)             // 73728

__device__ __forceinline__ void fa_stage_load(
    uint32_t stb, size_t base, int k0, int tid,
    const __half* __restrict__ Khi, const __half* __restrict__ Vhi)
{
    const int arr = tid >> 7, row = tid & 127;
    const __half* src = (arr == 0) ? Khi : Vhi;
    const __half* p = src + base + (size_t)(k0 + row) * D_;
    const uint32_t d = stb + arr * KARRB + row * FROWB;
    #pragma unroll
    for (int seg = 0; seg < 8; seg++)
        cp16(d + seg * 16, p + seg * 8);
}

#define LOADK(ks_, jg_, p_) do {                                               \
    _Pragma("unroll")                                                          \
    for (int t2 = 0; t2 < 4; t2++) {                                           \
        const uint32_t ba = stb + kb4                                          \
            + (uint32_t)(((jg_) + 2 * t2) * 8 * FROWB + (ks_) * 32);           \
        uint32_t rr[4];                                                        \
        ldsm4(rr, ba);                                                         \
        kh2[p_][2*t2][0] = rr[0]; kh2[p_][2*t2][1] = rr[1];                    \
        kh2[p_][2*t2+1][0] = rr[2]; kh2[p_][2*t2+1][1] = rr[3];                \
    }                                                                          \
} while (0)

#define LOADV(ks_, p_) do {                                                    \
    _Pragma("unroll")                                                          \
    for (int t2 = 0; t2 < 4; t2++) {                                           \
        const uint32_t va = stb + KARRB + vb4                                  \
            + (uint32_t)((ks_) * 16 * FROWB + 2 * t2 * 16);                    \
        uint32_t rr[4];                                                        \
        ldsm4t(rr, va);                                                        \
        vh2[p_][2*t2][0] = rr[0]; vh2[p_][2*t2][1] = rr[1];                    \
        vh2[p_][2*t2+1][0] = rr[2]; vh2[p_][2*t2+1][1] = rr[3];                \
    }                                                                          \
} while (0)

#define PSPLIT(ks_, p_) do {                                                   \
    split2h(sacc[2*(ks_)][0],   sacc[2*(ks_)][1],   pah2[p_][0], pal2[p_][0]); \
    split2h(sacc[2*(ks_)][2],   sacc[2*(ks_)][3],   pah2[p_][1], pal2[p_][1]); \
    split2h(sacc[2*(ks_)+1][0], sacc[2*(ks_)+1][1], pah2[p_][2], pal2[p_][2]); \
    split2h(sacc[2*(ks_)+1][2], sacc[2*(ks_)+1][3], pah2[p_][3], pal2[p_][3]); \
} while (0)

__global__ void __launch_bounds__(256, 1)
flash_hmma(const __half* __restrict__ Qhi, const __half* __restrict__ Qlo,
           const __half* __restrict__ Khi, const __half* __restrict__ Vhi,
           __half* __restrict__ chi, __half* __restrict__ clo)
{
    extern __shared__ uint32_t su[];
    const uint32_t sb = smem_u32(su);
    char* sc = (char*)su;

    const int tid = threadIdx.x, wid = tid >> 5, lid = tid & 31;
    const int g = lid >> 2, tc = lid & 3;
    const int bh = blockIdx.y;
    const int bx = (int)gridDim.x - 1 - (int)blockIdx.x;   // heavy tiles first
    const int b = bh / H_, h = bh % H_;
    const int q0 = bx * 128;
    const size_t base = (size_t)b * S_ * D_ + (size_t)h * DH_;
    const int wrow = q0 + wid * 16;
    const int ktiles = bx + 1;

    fa_stage_load(sb, base, 0, tid, Khi, Vhi);
    cp_commit();

    // stage Q through buffer 1 (Qhi at +0, Qlo at +KARRB)
    #pragma unroll
    for (int it = 0; it < 4; it++) {
        const int idx = tid + it * 256;
        const int row = idx >> 3, seg = idx & 7;
        const size_t e = base + (size_t)(q0 + row) * D_ + seg * 8;
        *(uint4*)(sc + FSTGB + row * FROWB + seg * 16)         = *(const uint4*)(Qhi + e);
        *(uint4*)(sc + FSTGB + KARRB + row * FROWB + seg * 16) = *(const uint4*)(Qlo + e);
    }
    __syncthreads();

    uint32_t qh[4][4], ql[4][4];
    {
        const uint32_t aa0 = sb + FSTGB
                           + (uint32_t)((wid * 16 + (lid & 15)) * FROWB + (lid >> 4) * 16);
        #pragma unroll
        for (int ks = 0; ks < 4; ks++) {
            ldsm4(qh[ks], aa0 + ks * 32);
            ldsm4(ql[ks], aa0 + KARRB + ks * 32);
        }
    }

    float oacc[8][4];
    #pragma unroll
    for (int j = 0; j < 8; j++)
        #pragma unroll
        for (int q = 0; q < 4; q++) oacc[j][q] = 0.0f;
    float m0r = -1e30f, m1r = -1e30f, l0r = 0.0f, l1r = 0.0f;

    const uint32_t kb4 = (uint32_t)(((lid & 7) + ((lid >> 4) << 3)) * FROWB
                                    + ((lid >> 3) & 1) * 16);
    const uint32_t vb4 = (uint32_t)((lid & 15) * FROWB + ((lid >> 4) & 1) * 16);

    for (int kt = 0; kt < ktiles; kt++) {
        const int k0 = kt * 128;
        cp_wait_all();
        __syncthreads();
        if (kt + 1 < ktiles) {
            fa_stage_load(sb + ((kt + 1) & 1) * FSTGB, base, k0 + 128, tid, Khi, Vhi);
            cp_commit();
        }

        const uint32_t stb = sb + (kt & 1) * FSTGB;

        // ---- S = Q @ K^T (2 MMAs per acc: qh.kh + ql.kh) ----
        float sacc[16][4];
        #pragma unroll
        for (int j = 0; j < 16; j++)
            #pragma unroll
            for (int q = 0; q < 4; q++) sacc[j][q] = 0.0f;

        {
            uint32_t kh2[2][8][2];
            LOADK(0, 0, 0);
            #pragma unroll
            for (int st = 0; st < 8; st++) {
                const int ks = st >> 1, jg = (st & 1) * 8, p = st & 1;
                if (st < 7) {
                    const int ks2 = (st + 1) >> 1, jg2 = ((st + 1) & 1) * 8;
                    LOADK(ks2, jg2, p ^ 1);
                }
                #pragma unroll
                for (int t = 0; t < 8; t++) mma16816(sacc[jg + t], qh[ks], kh2[p][t]);
                #pragma unroll
                for (int t = 0; t < 8; t++) mma16816(sacc[jg + t], ql[ks], kh2[p][t]);
            }
        }

        // ---- causal mask (diagonal tile only) ----
        if (k0 + 127 > wrow) {
            #pragma unroll
            for (int jn = 0; jn < 16; jn++) {
                const int c0 = k0 + jn * 8 + 2 * tc;
                const int r0g = wrow + g;
                if (c0     > r0g)     sacc[jn][0] = -1e30f;
                if (c0 + 1 > r0g)     sacc[jn][1] = -1e30f;
                if (c0     > r0g + 8) sacc[jn][2] = -1e30f;
                if (c0 + 1 > r0g + 8) sacc[jn][3] = -1e30f;
            }
        }

        // ---- online softmax (ex2) ----
        float mt0 = -1e30f, mt1 = -1e30f;
        #pragma unroll
        for (int jn = 0; jn < 16; jn += 2) {
            float u = fmaxf(fmaxf(sacc[jn][0], sacc[jn][1]),
                            fmaxf(sacc[jn+1][0], sacc[jn+1][1]));
            float v = fmaxf(fmaxf(sacc[jn][2], sacc[jn][3]),
                            fmaxf(sacc[jn+1][2], sacc[jn+1][3]));
            mt0 = fmaxf(mt0, u);
            mt1 = fmaxf(mt1, v);
        }
        mt0 = fmaxf(mt0, __shfl_xor_sync(0xffffffffu, mt0, 1));
        mt0 = fmaxf(mt0, __shfl_xor_sync(0xffffffffu, mt0, 2));
        mt1 = fmaxf(mt1, __shfl_xor_sync(0xffffffffu, mt1, 1));
        mt1 = fmaxf(mt1, __shfl_xor_sync(0xffffffffu, mt1, 2));

        const float mn0 = fmaxf(m0r, mt0), mn1 = fmaxf(m1r, mt1);
        const float al0 = ex2f(m0r - mn0), al1 = ex2f(m1r - mn1);
        m0r = mn0; m1r = mn1;

        #pragma unroll
        for (int jn = 0; jn < 16; jn++) {
            sacc[jn][0] = ex2f(sacc[jn][0] - mn0);
            sacc[jn][1] = ex2f(sacc[jn][1] - mn0);
            sacc[jn][2] = ex2f(sacc[jn][2] - mn1);
            sacc[jn][3] = ex2f(sacc[jn][3] - mn1);
        }
        float p0 = 0.0f, p1 = 0.0f, p2 = 0.0f, p3 = 0.0f;
        #pragma unroll
        for (int jn = 0; jn < 16; jn += 2) {
            p0 += sacc[jn][0] + sacc[jn][1];
            p1 += sacc[jn+1][0] + sacc[jn+1][1];
            p2 += sacc[jn][2] + sacc[jn][3];
            p3 += sacc[jn+1][2] + sacc[jn+1][3];
        }
        float ls0 = p0 + p1, ls1 = p2 + p3;
        ls0 += __shfl_xor_sync(0xffffffffu, ls0, 1);
        ls0 += __shfl_xor_sync(0xffffffffu, ls0, 2);
        ls1 += __shfl_xor_sync(0xffffffffu, ls1, 1);
        ls1 += __shfl_xor_sync(0xffffffffu, ls1, 2);
        l0r = l0r * al0 + ls0;
        l1r = l1r * al1 + ls1;

        #pragma unroll
        for (int jn = 0; jn < 8; jn++) {
            oacc[jn][0] *= al0; oacc[jn][1] *= al0;
            oacc[jn][2] *= al1; oacc[jn][3] *= al1;
        }

        // ---- O += P @ V (2 MMAs per acc; V and P-splits double-buffered) ----
        {
            uint32_t vh2[2][8][2];
            uint32_t pah2[2][4], pal2[2][4];
            LOADV(0, 0);
            PSPLIT(0, 0);
            #pragma unroll
            for (int ks = 0; ks < 8; ks++) {
                const int p = ks & 1;
                if (ks < 7) {
                    LOADV(ks + 1, p ^ 1);
                    PSPLIT(ks + 1, p ^ 1);
                }
                #pragma unroll
                for (int t = 0; t < 8; t++) mma16816(oacc[t], pah2[p], vh2[p][t]);
                #pragma unroll
                for (int t = 0; t < 8; t++) mma16816(oacc[t], pal2[p], vh2[p][t]);
            }
        }
    }

    const float inv0 = 1.0f / l0r, inv1 = 1.0f / l1r;
    const int row0 = q0 + wid * 16 + g;
    #pragma unroll
    for (int jn = 0; jn < 8; jn++) {
        const int c = jn * 8 + 2 * tc;
        uint32_t h0, l0, h1, l1;
        split2h(oacc[jn][0] * inv0, oacc[jn][1] * inv0, h0, l0);
        split2h(oacc[jn][2] * inv1, oacc[jn][3] * inv1, h1, l1);
        const size_t e0 = base + (size_t)row0 * D_ + c;
        const size_t e1 = base + (size_t)(row0 + 8) * D_ + c;
        *(uint32_t*)(chi + e0) = h0;
        *(uint32_t*)(clo + e0) = l0;
        *(uint32_t*)(chi + e1) = h1;
        *(uint32_t*)(clo + e1) = l1;
    }
}

// ---------------------------------------------------------------------------
// Launch
// ---------------------------------------------------------------------------
extern "C" void kernel_launch(void* const* d_in, const int* in_sizes, int n_in,
                              void* d_out, int out_size)
{
    const float* query = (const float*)d_in[0];
    const float* key   = (const float*)d_in[1];
    const float* value = (const float*)d_in[2];
    const float* Wq    = (const float*)d_in[4];
    const float* bq    = (const float*)d_in[5];
    const float* Wk    = (const float*)d_in[6];
    const float* bk    = (const float*)d_in[7];
    const float* Wv    = (const float*)d_in[8];
    const float* bv    = (const float*)d_in[9];
    const float* Wo    = (const float*)d_in[10];
    const float* bo    = (const float*)d_in[11];
    float* out = (float*)d_out;

    __half *inhi, *inlo, *qkvhi, *qkvlo, *chi, *clo, *whi;
    cudaGetSymbolAddress((void**)&inhi, g_inhi);
    cudaGetSymbolAddress((void**)&inlo, g_inlo);
    cudaGetSymbolAddress((void**)&qkvhi, g_qkvhi);
    cudaGetSymbolAddress((void**)&qkvlo, g_qkvlo);
    cudaGetSymbolAddress((void**)&chi, g_chi);
    cudaGetSymbolAddress((void**)&clo, g_clo);
    cudaGetSymbolAddress((void**)&whi, g_whi);

    cudaFuncSetAttribute(gemm_qkv, cudaFuncAttributeMaxDynamicSharedMemorySize, GEMM_SMEM);
    cudaFuncSetAttribute(gemm_o,   cudaFuncAttributeMaxDynamicSharedMemorySize, GEMM_SMEM);
    cudaFuncSetAttribute(flash_hmma, cudaFuncAttributeMaxDynamicSharedMemorySize, FAH_SMEM);

    prep_w<<<dim3(32, 32, 4), dim3(32, 8)>>>(Wq, Wk, Wv, Wo, whi);
    prep_in<<<dim3(MROWS * D_ / 4 / 256, 3), 256>>>(query, key, value, inhi, inlo);

    gemm_qkv<<<dim3(D_ / 128, MROWS / 128, 3), 256, GEMM_SMEM>>>(
        inhi, inlo, whi, bq, bk, bv, qkvhi, qkvlo);

    flash_hmma<<<dim3(S_ / 128, B_ * H_), 256, FAH_SMEM>>>(
        qkvhi, qkvlo,
        qkvhi + ISZ,
        qkvhi + 2 * ISZ,
        chi, clo);

    gemm_o<<<dim3(D_ / 128, MROWS / 128), 256, GEMM_SMEM>>>(
        chi, clo, whi + 3 * WSZ, bo, out);
}

// round 14
// speedup vs baseline: 1.6636x; 1.1580x over previous
#include <cuda_runtime.h>
#include <cuda_bf16.h>
#include <cuda_fp16.h>
#include <cstdint>

#define B_  2
#define S_  2048
#define D_  1024
#define H_  16
#define DH_ 64
#define MROWS (B_*S_)   // 4096
#define ISZ ((size_t)MROWS * D_)
#define WSZ ((size_t)D_ * D_)

// Scratch (allocation-free rule: __device__ globals). 16-bit payloads are fp16.
__device__ __half g_inhi[3 * MROWS * D_];
__device__ __half g_inlo[3 * MROWS * D_];
__device__ __half g_qkvhi[3 * MROWS * D_];
__device__ __half g_qkvlo[MROWS * D_];       // lo needed for Q only
__device__ __half g_chi[MROWS * D_];
__device__ __half g_whi[4][D_ * D_];

#define QSCALE (0.125f * 1.4426950408889634f)

// ---------------------------------------------------------------------------
// Helpers
// ---------------------------------------------------------------------------
__device__ __forceinline__ uint32_t smem_u32(const void* p) {
    uint32_t a;
    asm("{ .reg .u64 t; cvta.to.shared.u64 t, %1; cvt.u32.u64 %0, t; }"
        : "=r"(a) : "l"(p));
    return a;
}
__device__ __forceinline__ float ex2f(float x) {
    float r;
    asm("ex2.approx.f32 %0, %1;" : "=f"(r) : "f"(x));
    return r;
}
// fp16 MMA: D(16x8 fp32) += A(16x16 fp16) @ B(16x8 fp16)
__device__ __forceinline__ void mma16816(float* c, const uint32_t* a, const uint32_t* b) {
    asm volatile(
        "mma.sync.aligned.m16n8k16.row.col.f32.f16.f16.f32 "
        "{%0,%1,%2,%3}, {%4,%5,%6,%7}, {%8,%9}, {%0,%1,%2,%3};"
        : "+f"(c[0]), "+f"(c[1]), "+f"(c[2]), "+f"(c[3])
        : "r"(a[0]), "r"(a[1]), "r"(a[2]), "r"(a[3]), "r"(b[0]), "r"(b[1]));
}

// pack two fp32 -> fp16x2 (RN)
__device__ __forceinline__ uint32_t pack16(float x, float y) {
    uint32_t h;
    asm("cvt.rn.f16x2.f32 %0, %1, %2;" : "=r"(h) : "f"(y), "f"(x));
    return h;
}

// fp16 hi/lo split (RN): hi = rn16(x), lo = rn16(x - hi)
__device__ __forceinline__ void split2h(float x, float y, uint32_t& hi, uint32_t& lo) {
    uint32_t h = pack16(x, y);
    const __half2 hh = *reinterpret_cast<const __half2*>(&h);
    const float hx = __low2float(hh), hy = __high2float(hh);
    hi = h;
    lo = pack16(x - hx, y - hy);
}

__device__ __forceinline__ void cp16(uint32_t dst, const void* src) {
    asm volatile("cp.async.cg.shared.global [%0], [%1], 16;" :: "r"(dst), "l"(src));
}
__device__ __forceinline__ void cp_commit() {
    asm volatile("cp.async.commit_group;");
}
__device__ __forceinline__ void cp_wait_all() {
    asm volatile("cp.async.wait_group 0;");
}
__device__ __forceinline__ void ldsm4(uint32_t* r, uint32_t saddr) {
    asm volatile("ldmatrix.sync.aligned.m8n8.x4.shared.b16 {%0,%1,%2,%3}, [%4];"
        : "=r"(r[0]), "=r"(r[1]), "=r"(r[2]), "=r"(r[3]) : "r"(saddr));
}
__device__ __forceinline__ void ldsm4t(uint32_t* r, uint32_t saddr) {
    asm volatile("ldmatrix.sync.aligned.m8n8.x4.trans.shared.b16 {%0,%1,%2,%3}, [%4];"
        : "=r"(r[0]), "=r"(r[1]), "=r"(r[2]), "=r"(r[3]) : "r"(saddr));
}

// ---------------------------------------------------------------------------
// prep_w: W[k][n] fp32 -> Whi[n][k] fp16 RN (B operand: hi only)
// ---------------------------------------------------------------------------
__global__ void prep_w(const float* __restrict__ W0, const float* __restrict__ W1,
                       const float* __restrict__ W2, const float* __restrict__ W3,
                       __half* __restrict__ Whi)
{
    __shared__ float t[32][33];
    const int z = blockIdx.z;
    const float* W = (z == 0) ? W0 : (z == 1) ? W1 : (z == 2) ? W2 : W3;
    const size_t zoff = (size_t)z * D_ * D_;
    const int n0 = blockIdx.x * 32, k0 = blockIdx.y * 32;
    const int tx = threadIdx.x, ty = threadIdx.y;
    #pragma unroll
    for (int j = 0; j < 32; j += 8)
        t[ty + j][tx] = W[(size_t)(k0 + ty + j) * D_ + n0 + tx];
    __syncthreads();
    #pragma unroll
    for (int j = 0; j < 32; j += 8) {
        float v = t[tx][ty + j];
        Whi[zoff + (size_t)(n0 + ty + j) * D_ + k0 + tx] = __float2half_rn(v);
    }
}

// ---------------------------------------------------------------------------
// prep_in: fp32 [M,K] -> fp16 hi/lo (A operand: split), 3 inputs per launch
// ---------------------------------------------------------------------------
__global__ void prep_in(const float* __restrict__ q, const float* __restrict__ k,
                        const float* __restrict__ v,
                        __half* __restrict__ hi, __half* __restrict__ lo)
{
    const int z = blockIdx.y;
    const float* src = (z == 0) ? q : (z == 1) ? k : v;
    const size_t base4 = (size_t)z * (MROWS * D_ / 4);
    const size_t i = (size_t)blockIdx.x * 256 + threadIdx.x;
    float4 a = ((const float4*)src)[i];
    uint2 h2, l2;
    split2h(a.x, a.y, h2.x, l2.x);
    split2h(a.z, a.w, h2.y, l2.y);
    ((uint2*)hi)[base4 + i] = h2;
    ((uint2*)lo)[base4 + i] = l2;
}

// ---------------------------------------------------------------------------
// QKV GEMM: 2-stage cp.async + ldmatrix, fp16 2-MMA (A split, W hi).
// Stage = Ahi|Alo|Whi (3 arrays, 80B rows). CTA 128x128, BK=32, 2 CTAs/SM.
// ---------------------------------------------------------------------------
#define GPADB 80
#define ARR_B (128 * GPADB)
#define STG_B (3 * ARR_B)
#define GEMM_SMEM (2 * STG_B)            // 61440 B

__device__ __forceinline__ void gemm_stage_load(
    uint32_t st, int m0, int n0, int k0, int r, int s0,
    const __half* __restrict__ Ahi, const __half* __restrict__ Alo,
    const __half* __restrict__ Whi)
{
    #pragma unroll
    for (int i = 0; i < 2; i++) {
        const int seg = s0 + i;
        const uint32_t d = st + (uint32_t)(r * GPADB + seg * 16);
        const size_t ea = (size_t)(m0 + r) * D_ + k0 + seg * 8;
        const size_t eb = (size_t)(n0 + r) * D_ + k0 + seg * 8;
        cp16(d,             Ahi + ea);
        cp16(d + ARR_B,     Alo + ea);
        cp16(d + 2 * ARR_B, Whi + eb);
    }
}

__global__ void __launch_bounds__(256, 2)
gemm_qkv(const __half* __restrict__ inhi, const __half* __restrict__ inlo,
         const __half* __restrict__ whi,
         const float* __restrict__ bq, const float* __restrict__ bk,
         const float* __restrict__ bv,
         __half* __restrict__ outhi, __half* __restrict__ outlo)
{
    extern __shared__ uint32_t sg[];
    const uint32_t sb = smem_u32(sg);
    const int tid = threadIdx.x, wid = tid >> 5, lid = tid & 31;
    const int g = lid >> 2, tc = lid & 3;
    const int wm = wid & 1, wn = wid >> 1;
    const int m0 = blockIdx.y * 128, n0 = blockIdx.x * 128;
    const int z = blockIdx.z;

    const __half* Ahi = inhi + (size_t)z * ISZ;
    const __half* Alo = inlo + (size_t)z * ISZ;
    const __half* Whi = whi + (size_t)z * WSZ;
    const float* bias = (z == 0) ? bq : (z == 1) ? bk : bv;
    const float scale = (z == 0) ? QSCALE : 1.0f;
    __half* Ohi = outhi + (size_t)z * ISZ;

    const int r = tid >> 1, s0 = (tid & 1) * 2;
    const uint32_t a_lane = (uint32_t)((wm * 64 + (lid & 15)) * GPADB + (lid >> 4) * 16);
    const uint32_t b_lane = (uint32_t)((wn * 32 + (lid & 7) + ((lid >> 4) << 3)) * GPADB
                                       + ((lid >> 3) & 1) * 16);

    float acc[4][4][4];
    #pragma unroll
    for (int i = 0; i < 4; i++)
        #pragma unroll
        for (int j = 0; j < 4; j++)
            #pragma unroll
            for (int q = 0; q < 4; q++) acc[i][j][q] = 0.0f;

    gemm_stage_load(sb, m0, n0, 0, r, s0, Ahi, Alo, Whi);
    cp_commit();
    cp_wait_all();
    __syncthreads();

    const int NCH = D_ / 32;
    for (int ch = 0; ch < NCH; ch++) {
        const int cs = ch & 1;
        if (ch + 1 < NCH) {
            gemm_stage_load(sb + (cs ^ 1) * STG_B, m0, n0, (ch + 1) * 32, r, s0,
                            Ahi, Alo, Whi);
            cp_commit();
        }
        const uint32_t st = sb + cs * STG_B;
        #pragma unroll
        for (int ks = 0; ks < 2; ks++) {
            uint32_t bhf[4][2];
            #pragma unroll
            for (int jg = 0; jg < 4; jg += 2) {
                const uint32_t ba = st + 2 * ARR_B + b_lane
                                  + (uint32_t)(jg * 8 * GPADB + ks * 32);
                uint32_t rr[4];
                ldsm4(rr, ba);
                bhf[jg][0] = rr[0]; bhf[jg][1] = rr[1];
                bhf[jg+1][0] = rr[2]; bhf[jg+1][1] = rr[3];
            }
            uint32_t ah2[2][4], al2[2][4];
            const uint32_t aa0 = st + a_lane + (uint32_t)(ks * 32);
            ldsm4(ah2[0], aa0);
            ldsm4(al2[0], aa0 + ARR_B);
            #pragma unroll
            for (int i = 0; i < 4; i++) {
                const int p = i & 1;
                if (i < 3) {
                    const uint32_t aa = st + a_lane
                                      + (uint32_t)((i + 1) * 16 * GPADB + ks * 32);
                    ldsm4(ah2[p ^ 1], aa);
                    ldsm4(al2[p ^ 1], aa + ARR_B);
                }
                #pragma unroll
                for (int j = 0; j < 4; j++) mma16816(acc[i][j], ah2[p], bhf[j]);
                #pragma unroll
                for (int j = 0; j < 4; j++) mma16816(acc[i][j], al2[p], bhf[j]);
            }
        }
        if (ch + 1 < NCH) cp_wait_all();
        __syncthreads();
    }

    // epilogue: hi always; lo only for Q (z==0)
    #pragma unroll
    for (int j = 0; j < 4; j++) {
        const int n = n0 + wn * 32 + j * 8 + tc * 2;
        const float2 b2 = *(const float2*)(bias + n);
        #pragma unroll
        for (int i = 0; i < 4; i++) {
            const int m = m0 + wm * 64 + i * 16 + g;
            const float v0 = (acc[i][j][0] + b2.x) * scale;
            const float v1 = (acc[i][j][1] + b2.y) * scale;
            const float v2 = (acc[i][j][2] + b2.x) * scale;
            const float v3 = (acc[i][j][3] + b2.y) * scale;
            if (z == 0) {
                uint32_t h0, l0, h1, l1;
                split2h(v0, v1, h0, l0);
                split2h(v2, v3, h1, l1);
                *(uint32_t*)(Ohi + (size_t)m * D_ + n) = h0;
                *(uint32_t*)(outlo + (size_t)m * D_ + n) = l0;
                *(uint32_t*)(Ohi + (size_t)(m + 8) * D_ + n) = h1;
                *(uint32_t*)(outlo + (size_t)(m + 8) * D_ + n) = l1;
            } else {
                *(uint32_t*)(Ohi + (size_t)m * D_ + n) = pack16(v0, v1);
                *(uint32_t*)(Ohi + (size_t)(m + 8) * D_ + n) = pack16(v2, v3);
            }
        }
    }
}

// ---------------------------------------------------------------------------
// O projection GEMM: A hi-only (ctx fp16), 1 MMA per acc pair.
// Stage = Ahi|Whi (2 arrays). fp32 output + bias.
// ---------------------------------------------------------------------------
#define OSTG_B (2 * ARR_B)
#define GEMMO_SMEM (2 * OSTG_B)          // 40960 B

__global__ void __launch_bounds__(256, 2)
gemm_o(const __half* __restrict__ Ahi, const __half* __restrict__ Whi,
       const float* __restrict__ bias, float* __restrict__ C)
{
    extern __shared__ uint32_t sg[];
    const uint32_t sb = smem_u32(sg);
    const int tid = threadIdx.x, wid = tid >> 5, lid = tid & 31;
    const int g = lid >> 2, tc = lid & 3;
    const int wm = wid & 1, wn = wid >> 1;
    const int m0 = blockIdx.y * 128, n0 = blockIdx.x * 128;

    const int r = tid >> 1, s0 = (tid & 1) * 2;
    const uint32_t a_lane = (uint32_t)((wm * 64 + (lid & 15)) * GPADB + (lid >> 4) * 16);
    const uint32_t b_lane = (uint32_t)((wn * 32 + (lid & 7) + ((lid >> 4) << 3)) * GPADB
                                       + ((lid >> 3) & 1) * 16);

    float acc[4][4][4];
    #pragma unroll
    for (int i = 0; i < 4; i++)
        #pragma unroll
        for (int j = 0; j < 4; j++)
            #pragma unroll
            for (int q = 0; q < 4; q++) acc[i][j][q] = 0.0f;

    // stage 0
    #pragma unroll
    for (int i = 0; i < 2; i++) {
        const int seg = s0 + i;
        const uint32_t d = sb + (uint32_t)(r * GPADB + seg * 16);
        cp16(d,         Ahi + (size_t)(m0 + r) * D_ + seg * 8);
        cp16(d + ARR_B, Whi + (size_t)(n0 + r) * D_ + seg * 8);
    }
    cp_commit();
    cp_wait_all();
    __syncthreads();

    const int NCH = D_ / 32;
    for (int ch = 0; ch < NCH; ch++) {
        const int cs = ch & 1;
        if (ch + 1 < NCH) {
            const int k0 = (ch + 1) * 32;
            const uint32_t st2 = sb + (cs ^ 1) * OSTG_B;
            #pragma unroll
            for (int i = 0; i < 2; i++) {
                const int seg = s0 + i;
                const uint32_t d = st2 + (uint32_t)(r * GPADB + seg * 16);
                cp16(d,         Ahi + (size_t)(m0 + r) * D_ + k0 + seg * 8);
                cp16(d + ARR_B, Whi + (size_t)(n0 + r) * D_ + k0 + seg * 8);
            }
            cp_commit();
        }
        const uint32_t st = sb + cs * OSTG_B;
        #pragma unroll
        for (int ks = 0; ks < 2; ks++) {
            uint32_t bhf[4][2];
            #pragma unroll
            for (int jg = 0; jg < 4; jg += 2) {
                const uint32_t ba = st + ARR_B + b_lane
                                  + (uint32_t)(jg * 8 * GPADB + ks * 32);
                uint32_t rr[4];
                ldsm4(rr, ba);
                bhf[jg][0] = rr[0]; bhf[jg][1] = rr[1];
                bhf[jg+1][0] = rr[2]; bhf[jg+1][1] = rr[3];
            }
            uint32_t ah2[2][4];
            ldsm4(ah2[0], st + a_lane + (uint32_t)(ks * 32));
            #pragma unroll
            for (int i = 0; i < 4; i++) {
                const int p = i & 1;
                if (i < 3)
                    ldsm4(ah2[p ^ 1], st + a_lane
                                    + (uint32_t)((i + 1) * 16 * GPADB + ks * 32));
                #pragma unroll
                for (int j = 0; j < 4; j++) mma16816(acc[i][j], ah2[p], bhf[j]);
            }
        }
        if (ch + 1 < NCH) cp_wait_all();
        __syncthreads();
    }

    #pragma unroll
    for (int j = 0; j < 4; j++) {
        const int n = n0 + wn * 32 + j * 8 + tc * 2;
        const float2 b2 = *(const float2*)(bias + n);
        #pragma unroll
        for (int i = 0; i < 4; i++) {
            const int m = m0 + wm * 64 + i * 16 + g;
            float2 o0, o1;
            o0.x = acc[i][j][0] + b2.x; o0.y = acc[i][j][1] + b2.y;
            o1.x = acc[i][j][2] + b2.x; o1.y = acc[i][j][3] + b2.y;
            *(float2*)(C + (size_t)m * D_ + n) = o0;
            *(float2*)(C + (size_t)(m + 8) * D_ + n) = o1;
        }
    }
}

// ---------------------------------------------------------------------------
// HMMA flash attention: kv tile 128, K/V hi-only, Q fp16 hi/lo,
// P hi-only (RN cvt, no split). ctx written hi-only. 1 CTA/SM.
// smem: 2 stages x (Khi|Vhi) = 73728 B; Q stages through buffer 1.
// ---------------------------------------------------------------------------
#define FROWB 144
#define KARRB (128 * FROWB)              // 18432
#define FSTGB (2 * KARRB)                // 36864
#define FAH_SMEM (2 * FSTGB)             // 73728

__device__ __forceinline__ void fa_stage_load(
    uint32_t stb, size_t base, int k0, int tid,
    const __half* __restrict__ Khi, const __half* __restrict__ Vhi)
{
    const int arr = tid >> 7, row = tid & 127;
    const __half* src = (arr == 0) ? Khi : Vhi;
    const __half* p = src + base + (size_t)(k0 + row) * D_;
    const uint32_t d = stb + arr * KARRB + row * FROWB;
    #pragma unroll
    for (int seg = 0; seg < 8; seg++)
        cp16(d + seg * 16, p + seg * 8);
}

#define LOADK(ks_, jg_, p_) do {                                               \
    _Pragma("unroll")                                                          \
    for (int t2 = 0; t2 < 4; t2++) {                                           \
        const uint32_t ba = stb + kb4                                          \
            + (uint32_t)(((jg_) + 2 * t2) * 8 * FROWB + (ks_) * 32);           \
        uint32_t rr[4];                                                        \
        ldsm4(rr, ba);                                                         \
        kh2[p_][2*t2][0] = rr[0]; kh2[p_][2*t2][1] = rr[1];                    \
        kh2[p_][2*t2+1][0] = rr[2]; kh2[p_][2*t2+1][1] = rr[3];                \
    }                                                                          \
} while (0)

#define LOADV(ks_, p_) do {                                                    \
    _Pragma("unroll")                                                          \
    for (int t2 = 0; t2 < 4; t2++) {                                           \
        const uint32_t va = stb + KARRB + vb4                                  \
            + (uint32_t)((ks_) * 16 * FROWB + 2 * t2 * 16);                    \
        uint32_t rr[4];                                                        \
        ldsm4t(rr, va);                                                        \
        vh2[p_][2*t2][0] = rr[0]; vh2[p_][2*t2][1] = rr[1];                    \
        vh2[p_][2*t2+1][0] = rr[2]; vh2[p_][2*t2+1][1] = rr[3];                \
    }                                                                          \
} while (0)

#define PCVT(ks_, p_) do {                                                     \
    pah2[p_][0] = pack16(sacc[2*(ks_)][0],   sacc[2*(ks_)][1]);                \
    pah2[p_][1] = pack16(sacc[2*(ks_)][2],   sacc[2*(ks_)][3]);                \
    pah2[p_][2] = pack16(sacc[2*(ks_)+1][0], sacc[2*(ks_)+1][1]);              \
    pah2[p_][3] = pack16(sacc[2*(ks_)+1][2], sacc[2*(ks_)+1][3]);              \
} while (0)

__global__ void __launch_bounds__(256, 1)
flash_hmma(const __half* __restrict__ Qhi, const __half* __restrict__ Qlo,
           const __half* __restrict__ Khi, const __half* __restrict__ Vhi,
           __half* __restrict__ chi)
{
    extern __shared__ uint32_t su[];
    const uint32_t sb = smem_u32(su);
    char* sc = (char*)su;

    const int tid = threadIdx.x, wid = tid >> 5, lid = tid & 31;
    const int g = lid >> 2, tc = lid & 3;
    const int bh = blockIdx.y;
    const int bx = (int)gridDim.x - 1 - (int)blockIdx.x;   // heavy tiles first
    const int b = bh / H_, h = bh % H_;
    const int q0 = bx * 128;
    const size_t base = (size_t)b * S_ * D_ + (size_t)h * DH_;
    const int wrow = q0 + wid * 16;
    const int ktiles = bx + 1;

    fa_stage_load(sb, base, 0, tid, Khi, Vhi);
    cp_commit();

    // stage Q through buffer 1 (Qhi at +0, Qlo at +KARRB)
    #pragma unroll
    for (int it = 0; it < 4; it++) {
        const int idx = tid + it * 256;
        const int row = idx >> 3, seg = idx & 7;
        const size_t e = base + (size_t)(q0 + row) * D_ + seg * 8;
        *(uint4*)(sc + FSTGB + row * FROWB + seg * 16)         = *(const uint4*)(Qhi + e);
        *(uint4*)(sc + FSTGB + KARRB + row * FROWB + seg * 16) = *(const uint4*)(Qlo + e);
    }
    __syncthreads();

    uint32_t qh[4][4], ql[4][4];
    {
        const uint32_t aa0 = sb + FSTGB
                           + (uint32_t)((wid * 16 + (lid & 15)) * FROWB + (lid >> 4) * 16);
        #pragma unroll
        for (int ks = 0; ks < 4; ks++) {
            ldsm4(qh[ks], aa0 + ks * 32);
            ldsm4(ql[ks], aa0 + KARRB + ks * 32);
        }
    }

    float oacc[8][4];
    #pragma unroll
    for (int j = 0; j < 8; j++)
        #pragma unroll
        for (int q = 0; q < 4; q++) oacc[j][q] = 0.0f;
    float m0r = -1e30f, m1r = -1e30f, l0r = 0.0f, l1r = 0.0f;

    const uint32_t kb4 = (uint32_t)(((lid & 7) + ((lid >> 4) << 3)) * FROWB
                                    + ((lid >> 3) & 1) * 16);
    const uint32_t vb4 = (uint32_t)((lid & 15) * FROWB + ((lid >> 4) & 1) * 16);

    for (int kt = 0; kt < ktiles; kt++) {
        const int k0 = kt * 128;
        cp_wait_all();
        __syncthreads();
        if (kt + 1 < ktiles) {
            fa_stage_load(sb + ((kt + 1) & 1) * FSTGB, base, k0 + 128, tid, Khi, Vhi);
            cp_commit();
        }

        const uint32_t stb = sb + (kt & 1) * FSTGB;

        // ---- S = Q @ K^T (2 MMAs per acc) ----
        float sacc[16][4];
        #pragma unroll
        for (int j = 0; j < 16; j++)
            #pragma unroll
            for (int q = 0; q < 4; q++) sacc[j][q] = 0.0f;

        {
            uint32_t kh2[2][8][2];
            LOADK(0, 0, 0);
            #pragma unroll
            for (int st = 0; st < 8; st++) {
                const int ks = st >> 1, jg = (st & 1) * 8, p = st & 1;
                if (st < 7) {
                    const int ks2 = (st + 1) >> 1, jg2 = ((st + 1) & 1) * 8;
                    LOADK(ks2, jg2, p ^ 1);
                }
                #pragma unroll
                for (int t = 0; t < 8; t++) mma16816(sacc[jg + t], qh[ks], kh2[p][t]);
                #pragma unroll
                for (int t = 0; t < 8; t++) mma16816(sacc[jg + t], ql[ks], kh2[p][t]);
            }
        }

        // ---- causal mask (diagonal tile only) ----
        if (k0 + 127 > wrow) {
            #pragma unroll
            for (int jn = 0; jn < 16; jn++) {
                const int c0 = k0 + jn * 8 + 2 * tc;
                const int r0g = wrow + g;
                if (c0     > r0g)     sacc[jn][0] = -1e30f;
                if (c0 + 1 > r0g)     sacc[jn][1] = -1e30f;
                if (c0     > r0g + 8) sacc[jn][2] = -1e30f;
                if (c0 + 1 > r0g + 8) sacc[jn][3] = -1e30f;
            }
        }

        // ---- online softmax (ex2) ----
        float mt0 = -1e30f, mt1 = -1e30f;
        #pragma unroll
        for (int jn = 0; jn < 16; jn += 2) {
            float u = fmaxf(fmaxf(sacc[jn][0], sacc[jn][1]),
                            fmaxf(sacc[jn+1][0], sacc[jn+1][1]));
            float v = fmaxf(fmaxf(sacc[jn][2], sacc[jn][3]),
                            fmaxf(sacc[jn+1][2], sacc[jn+1][3]));
            mt0 = fmaxf(mt0, u);
            mt1 = fmaxf(mt1, v);
        }
        mt0 = fmaxf(mt0, __shfl_xor_sync(0xffffffffu, mt0, 1));
        mt0 = fmaxf(mt0, __shfl_xor_sync(0xffffffffu, mt0, 2));
        mt1 = fmaxf(mt1, __shfl_xor_sync(0xffffffffu, mt1, 1));
        mt1 = fmaxf(mt1, __shfl_xor_sync(0xffffffffu, mt1, 2));

        const float mn0 = fmaxf(m0r, mt0), mn1 = fmaxf(m1r, mt1);
        const float al0 = ex2f(m0r - mn0), al1 = ex2f(m1r - mn1);
        m0r = mn0; m1r = mn1;

        #pragma unroll
        for (int jn = 0; jn < 16; jn++) {
            sacc[jn][0] = ex2f(sacc[jn][0] - mn0);
            sacc[jn][1] = ex2f(sacc[jn][1] - mn0);
            sacc[jn][2] = ex2f(sacc[jn][2] - mn1);
            sacc[jn][3] = ex2f(sacc[jn][3] - mn1);
        }
        float p0 = 0.0f, p1 = 0.0f, p2 = 0.0f, p3 = 0.0f;
        #pragma unroll
        for (int jn = 0; jn < 16; jn += 2) {
            p0 += sacc[jn][0] + sacc[jn][1];
            p1 += sacc[jn+1][0] + sacc[jn+1][1];
            p2 += sacc[jn][2] + sacc[jn][3];
            p3 += sacc[jn+1][2] + sacc[jn+1][3];
        }
        float ls0 = p0 + p1, ls1 = p2 + p3;
        ls0 += __shfl_xor_sync(0xffffffffu, ls0, 1);
        ls0 += __shfl_xor_sync(0xffffffffu, ls0, 2);
        ls1 += __shfl_xor_sync(0xffffffffu, ls1, 1);
        ls1 += __shfl_xor_sync(0xffffffffu, ls1, 2);
        l0r = l0r * al0 + ls0;
        l1r = l1r * al1 + ls1;

        #pragma unroll
        for (int jn = 0; jn < 8; jn++) {
            oacc[jn][0] *= al0; oacc[jn][1] *= al0;
            oacc[jn][2] *= al1; oacc[jn][3] *= al1;
        }

        // ---- O += P @ V (P hi-only: 1 MMA per acc; V+P double-buffered) ----
        {
            uint32_t vh2[2][8][2];
            uint32_t pah2[2][4];
            LOADV(0, 0);
            PCVT(0, 0);
            #pragma unroll
            for (int ks = 0; ks < 8; ks++) {
                const int p = ks & 1;
                if (ks < 7) {
                    LOADV(ks + 1, p ^ 1);
                    PCVT(ks + 1, p ^ 1);
                }
                #pragma unroll
                for (int t = 0; t < 8; t++) mma16816(oacc[t], pah2[p], vh2[p][t]);
            }
        }
    }

    // normalize + store ctx hi-only fp16
    const float inv0 = 1.0f / l0r, inv1 = 1.0f / l1r;
    const int row0 = q0 + wid * 16 + g;
    #pragma unroll
    for (int jn = 0; jn < 8; jn++) {
        const int c = jn * 8 + 2 * tc;
        *(uint32_t*)(chi + base + (size_t)row0 * D_ + c) =
            pack16(oacc[jn][0] * inv0, oacc[jn][1] * inv0);
        *(uint32_t*)(chi + base + (size_t)(row0 + 8) * D_ + c) =
            pack16(oacc[jn][2] * inv1, oacc[jn][3] * inv1);
    }
}

// ---------------------------------------------------------------------------
// Launch
// ---------------------------------------------------------------------------
extern "C" void kernel_launch(void* const* d_in, const int* in_sizes, int n_in,
                              void* d_out, int out_size)
{
    const float* query = (const float*)d_in[0];
    const float* key   = (const float*)d_in[1];
    const float* value = (const float*)d_in[2];
    const float* Wq    = (const float*)d_in[4];
    const float* bq    = (const float*)d_in[5];
    const float* Wk    = (const float*)d_in[6];
    const float* bk    = (const float*)d_in[7];
    const float* Wv    = (const float*)d_in[8];
    const float* bv    = (const float*)d_in[9];
    const float* Wo    = (const float*)d_in[10];
    const float* bo    = (const float*)d_in[11];
    float* out = (float*)d_out;

    __half *inhi, *inlo, *qkvhi, *qkvlo, *chi, *whi;
    cudaGetSymbolAddress((void**)&inhi, g_inhi);
    cudaGetSymbolAddress((void**)&inlo, g_inlo);
    cudaGetSymbolAddress((void**)&qkvhi, g_qkvhi);
    cudaGetSymbolAddress((void**)&qkvlo, g_qkvlo);
    cudaGetSymbolAddress((void**)&chi, g_chi);
    cudaGetSymbolAddress((void**)&whi, g_whi);

    cudaFuncSetAttribute(gemm_qkv, cudaFuncAttributeMaxDynamicSharedMemorySize, GEMM_SMEM);
    cudaFuncSetAttribute(gemm_o,   cudaFuncAttributeMaxDynamicSharedMemorySize, GEMMO_SMEM);
    cudaFuncSetAttribute(flash_hmma, cudaFuncAttributeMaxDynamicSharedMemorySize, FAH_SMEM);

    prep_w<<<dim3(32, 32, 4), dim3(32, 8)>>>(Wq, Wk, Wv, Wo, whi);
    prep_in<<<dim3(MROWS * D_ / 4 / 256, 3), 256>>>(query, key, value, inhi, inlo);

    gemm_qkv<<<dim3(D_ / 128, MROWS / 128, 3), 256, GEMM_SMEM>>>(
        inhi, inlo, whi, bq, bk, bv, qkvhi, qkvlo);

    flash_hmma<<<dim3(S_ / 128, B_ * H_), 256, FAH_SMEM>>>(
        qkvhi, qkvlo,
        qkvhi + ISZ,
        qkvhi + 2 * ISZ,
        chi);

    gemm_o<<<dim3(D_ / 128, MROWS / 128), 256, GEMMO_SMEM>>>(
        chi, whi + 3 * WSZ, bo, out);
}

// round 15
// speedup vs baseline: 2.0947x; 1.2591x over previous
#include <cuda_runtime.h>
#include <cuda_bf16.h>
#include <cuda_fp16.h>
#include <cstdint>

#define B_  2
#define S_  2048
#define D_  1024
#define H_  16
#define DH_ 64
#define MROWS (B_*S_)   // 4096
#define ISZ ((size_t)MROWS * D_)
#define WSZ ((size_t)D_ * D_)

// Scratch (allocation-free rule: __device__ globals). 16-bit payloads are fp16.
__device__ __half g_inhi[3 * MROWS * D_];    // inputs, hi only
__device__ __half g_qkvhi[3 * MROWS * D_];
__device__ __half g_qkvlo[MROWS * D_];       // lo needed for Q only
__device__ __half g_chi[MROWS * D_];
__device__ __half g_whi[4][D_ * D_];

#define QSCALE (0.125f * 1.4426950408889634f)

// ---------------------------------------------------------------------------
// Helpers
// ---------------------------------------------------------------------------
__device__ __forceinline__ uint32_t smem_u32(const void* p) {
    uint32_t a;
    asm("{ .reg .u64 t; cvta.to.shared.u64 t, %1; cvt.u32.u64 %0, t; }"
        : "=r"(a) : "l"(p));
    return a;
}
__device__ __forceinline__ float ex2f(float x) {
    float r;
    asm("ex2.approx.f32 %0, %1;" : "=f"(r) : "f"(x));
    return r;
}
// fp16 MMA: D(16x8 fp32) += A(16x16 fp16) @ B(16x8 fp16)
__device__ __forceinline__ void mma16816(float* c, const uint32_t* a, const uint32_t* b) {
    asm volatile(
        "mma.sync.aligned.m16n8k16.row.col.f32.f16.f16.f32 "
        "{%0,%1,%2,%3}, {%4,%5,%6,%7}, {%8,%9}, {%0,%1,%2,%3};"
        : "+f"(c[0]), "+f"(c[1]), "+f"(c[2]), "+f"(c[3])
        : "r"(a[0]), "r"(a[1]), "r"(a[2]), "r"(a[3]), "r"(b[0]), "r"(b[1]));
}

// pack two fp32 -> fp16x2 (RN)
__device__ __forceinline__ uint32_t pack16(float x, float y) {
    uint32_t h;
    asm("cvt.rn.f16x2.f32 %0, %1, %2;" : "=r"(h) : "f"(y), "f"(x));
    return h;
}

// fp16 hi/lo split (RN): hi = rn16(x), lo = rn16(x - hi)
__device__ __forceinline__ void split2h(float x, float y, uint32_t& hi, uint32_t& lo) {
    uint32_t h = pack16(x, y);
    const __half2 hh = *reinterpret_cast<const __half2*>(&h);
    const float hx = __low2float(hh), hy = __high2float(hh);
    hi = h;
    lo = pack16(x - hx, y - hy);
}

__device__ __forceinline__ void cp16(uint32_t dst, const void* src) {
    asm volatile("cp.async.cg.shared.global [%0], [%1], 16;" :: "r"(dst), "l"(src));
}
__device__ __forceinline__ void cp_commit() {
    asm volatile("cp.async.commit_group;");
}
__device__ __forceinline__ void cp_wait_all() {
    asm volatile("cp.async.wait_group 0;");
}
__device__ __forceinline__ void ldsm4(uint32_t* r, uint32_t saddr) {
    asm volatile("ldmatrix.sync.aligned.m8n8.x4.shared.b16 {%0,%1,%2,%3}, [%4];"
        : "=r"(r[0]), "=r"(r[1]), "=r"(r[2]), "=r"(r[3]) : "r"(saddr));
}
__device__ __forceinline__ void ldsm4t(uint32_t* r, uint32_t saddr) {
    asm volatile("ldmatrix.sync.aligned.m8n8.x4.trans.shared.b16 {%0,%1,%2,%3}, [%4];"
        : "=r"(r[0]), "=r"(r[1]), "=r"(r[2]), "=r"(r[3]) : "r"(saddr));
}

// ---------------------------------------------------------------------------
// prep_w: W[k][n] fp32 -> Whi[n][k] fp16 RN (hi only)
// ---------------------------------------------------------------------------
__global__ void prep_w(const float* __restrict__ W0, const float* __restrict__ W1,
                       const float* __restrict__ W2, const float* __restrict__ W3,
                       __half* __restrict__ Whi)
{
    __shared__ float t[32][33];
    const int z = blockIdx.z;
    const float* W = (z == 0) ? W0 : (z == 1) ? W1 : (z == 2) ? W2 : W3;
    const size_t zoff = (size_t)z * D_ * D_;
    const int n0 = blockIdx.x * 32, k0 = blockIdx.y * 32;
    const int tx = threadIdx.x, ty = threadIdx.y;
    #pragma unroll
    for (int j = 0; j < 32; j += 8)
        t[ty + j][tx] = W[(size_t)(k0 + ty + j) * D_ + n0 + tx];
    __syncthreads();
    #pragma unroll
    for (int j = 0; j < 32; j += 8) {
        float v = t[tx][ty + j];
        Whi[zoff + (size_t)(n0 + ty + j) * D_ + k0 + tx] = __float2half_rn(v);
    }
}

// ---------------------------------------------------------------------------
// prep_in: fp32 [M,K] -> fp16 hi only, 3 inputs in one launch (blockIdx.y)
// ---------------------------------------------------------------------------
__global__ void prep_in(const float* __restrict__ q, const float* __restrict__ k,
                        const float* __restrict__ v, __half* __restrict__ hi)
{
    const int z = blockIdx.y;
    const float* src = (z == 0) ? q : (z == 1) ? k : v;
    const size_t base4 = (size_t)z * (MROWS * D_ / 4);
    const size_t i = (size_t)blockIdx.x * 256 + threadIdx.x;
    float4 a = ((const float4*)src)[i];
    uint2 h2;
    h2.x = pack16(a.x, a.y);
    h2.y = pack16(a.z, a.w);
    ((uint2*)hi)[base4 + i] = h2;
}

// ---------------------------------------------------------------------------
// Hi-only GEMM mainloop: 2-stage cp.async + ldmatrix, 1 MMA per acc step.
// Stage = Ahi|Whi (2 arrays, 80B rows). CTA 128x128, BK=32, 2 CTAs/SM.
// ---------------------------------------------------------------------------
#define GPADB 80
#define ARR_B (128 * GPADB)
#define OSTG_B (2 * ARR_B)
#define GEMM_SMEM (2 * OSTG_B)           // 40960 B

__device__ __forceinline__ void gemm_mainloop_hi(
    uint32_t sb, int tid, int m0, int n0,
    const __half* __restrict__ Ahi, const __half* __restrict__ Whi,
    float acc[4][4][4])
{
    const int wid = tid >> 5, lid = tid & 31;
    const int wm = wid & 1, wn = wid >> 1;
    const int r = tid >> 1, s0 = (tid & 1) * 2;
    const uint32_t a_lane = (uint32_t)((wm * 64 + (lid & 15)) * GPADB + (lid >> 4) * 16);
    const uint32_t b_lane = (uint32_t)((wn * 32 + (lid & 7) + ((lid >> 4) << 3)) * GPADB
                                       + ((lid >> 3) & 1) * 16);

    // stage 0
    #pragma unroll
    for (int i = 0; i < 2; i++) {
        const int seg = s0 + i;
        const uint32_t d = sb + (uint32_t)(r * GPADB + seg * 16);
        cp16(d,         Ahi + (size_t)(m0 + r) * D_ + seg * 8);
        cp16(d + ARR_B, Whi + (size_t)(n0 + r) * D_ + seg * 8);
    }
    cp_commit();
    cp_wait_all();
    __syncthreads();

    const int NCH = D_ / 32;
    for (int ch = 0; ch < NCH; ch++) {
        const int cs = ch & 1;
        if (ch + 1 < NCH) {
            const int k0 = (ch + 1) * 32;
            const uint32_t st2 = sb + (cs ^ 1) * OSTG_B;
            #pragma unroll
            for (int i = 0; i < 2; i++) {
                const int seg = s0 + i;
                const uint32_t d = st2 + (uint32_t)(r * GPADB + seg * 16);
                cp16(d,         Ahi + (size_t)(m0 + r) * D_ + k0 + seg * 8);
                cp16(d + ARR_B, Whi + (size_t)(n0 + r) * D_ + k0 + seg * 8);
            }
            cp_commit();
        }
        const uint32_t st = sb + cs * OSTG_B;
        #pragma unroll
        for (int ks = 0; ks < 2; ks++) {
            uint32_t bhf[4][2];
            #pragma unroll
            for (int jg = 0; jg < 4; jg += 2) {
                const uint32_t ba = st + ARR_B + b_lane
                                  + (uint32_t)(jg * 8 * GPADB + ks * 32);
                uint32_t rr[4];
                ldsm4(rr, ba);
                bhf[jg][0] = rr[0]; bhf[jg][1] = rr[1];
                bhf[jg+1][0] = rr[2]; bhf[jg+1][1] = rr[3];
            }
            uint32_t ah2[2][4];
            ldsm4(ah2[0], st + a_lane + (uint32_t)(ks * 32));
            #pragma unroll
            for (int i = 0; i < 4; i++) {
                const int p = i & 1;
                if (i < 3)
                    ldsm4(ah2[p ^ 1], st + a_lane
                                    + (uint32_t)((i + 1) * 16 * GPADB + ks * 32));
                #pragma unroll
                for (int j = 0; j < 4; j++) mma16816(acc[i][j], ah2[p], bhf[j]);
            }
        }
        if (ch + 1 < NCH) cp_wait_all();
        __syncthreads();
    }
}

// ---------------------------------------------------------------------------
// QKV GEMM: hi-only A and W; split output only for Q (z==0).
// ---------------------------------------------------------------------------
__global__ void __launch_bounds__(256, 2)
gemm_qkv(const __half* __restrict__ inhi, const __half* __restrict__ whi,
         const float* __restrict__ bq, const float* __restrict__ bk,
         const float* __restrict__ bv,
         __half* __restrict__ outhi, __half* __restrict__ outlo)
{
    extern __shared__ uint32_t sg[];
    const uint32_t sb = smem_u32(sg);
    const int tid = threadIdx.x, wid = tid >> 5, lid = tid & 31;
    const int g = lid >> 2, tc = lid & 3;
    const int wm = wid & 1, wn = wid >> 1;
    const int m0 = blockIdx.y * 128, n0 = blockIdx.x * 128;
    const int z = blockIdx.z;

    const __half* Ahi = inhi + (size_t)z * ISZ;
    const __half* Whi = whi + (size_t)z * WSZ;
    const float* bias = (z == 0) ? bq : (z == 1) ? bk : bv;
    const float scale = (z == 0) ? QSCALE : 1.0f;
    __half* Ohi = outhi + (size_t)z * ISZ;

    float acc[4][4][4];
    #pragma unroll
    for (int i = 0; i < 4; i++)
        #pragma unroll
        for (int j = 0; j < 4; j++)
            #pragma unroll
            for (int q = 0; q < 4; q++) acc[i][j][q] = 0.0f;

    gemm_mainloop_hi(sb, tid, m0, n0, Ahi, Whi, acc);

    #pragma unroll
    for (int j = 0; j < 4; j++) {
        const int n = n0 + wn * 32 + j * 8 + tc * 2;
        const float2 b2 = *(const float2*)(bias + n);
        #pragma unroll
        for (int i = 0; i < 4; i++) {
            const int m = m0 + wm * 64 + i * 16 + g;
            const float v0 = (acc[i][j][0] + b2.x) * scale;
            const float v1 = (acc[i][j][1] + b2.y) * scale;
            const float v2 = (acc[i][j][2] + b2.x) * scale;
            const float v3 = (acc[i][j][3] + b2.y) * scale;
            if (z == 0) {
                uint32_t h0, l0, h1, l1;
                split2h(v0, v1, h0, l0);
                split2h(v2, v3, h1, l1);
                *(uint32_t*)(Ohi + (size_t)m * D_ + n) = h0;
                *(uint32_t*)(outlo + (size_t)m * D_ + n) = l0;
                *(uint32_t*)(Ohi + (size_t)(m + 8) * D_ + n) = h1;
                *(uint32_t*)(outlo + (size_t)(m + 8) * D_ + n) = l1;
            } else {
                *(uint32_t*)(Ohi + (size_t)m * D_ + n) = pack16(v0, v1);
                *(uint32_t*)(Ohi + (size_t)(m + 8) * D_ + n) = pack16(v2, v3);
            }
        }
    }
}

// ---------------------------------------------------------------------------
// O projection GEMM: hi-only, fp32 output + bias.
// ---------------------------------------------------------------------------
__global__ void __launch_bounds__(256, 2)
gemm_o(const __half* __restrict__ Ahi, const __half* __restrict__ Whi,
       const float* __restrict__ bias, float* __restrict__ C)
{
    extern __shared__ uint32_t sg[];
    const uint32_t sb = smem_u32(sg);
    const int tid = threadIdx.x, wid = tid >> 5, lid = tid & 31;
    const int g = lid >> 2, tc = lid & 3;
    const int wm = wid & 1, wn = wid >> 1;
    const int m0 = blockIdx.y * 128, n0 = blockIdx.x * 128;

    float acc[4][4][4];
    #pragma unroll
    for (int i = 0; i < 4; i++)
        #pragma unroll
        for (int j = 0; j < 4; j++)
            #pragma unroll
            for (int q = 0; q < 4; q++) acc[i][j][q] = 0.0f;

    gemm_mainloop_hi(sb, tid, m0, n0, Ahi, Whi, acc);

    #pragma unroll
    for (int j = 0; j < 4; j++) {
        const int n = n0 + wn * 32 + j * 8 + tc * 2;
        const float2 b2 = *(const float2*)(bias + n);
        #pragma unroll
        for (int i = 0; i < 4; i++) {
            const int m = m0 + wm * 64 + i * 16 + g;
            float2 o0, o1;
            o0.x = acc[i][j][0] + b2.x; o0.y = acc[i][j][1] + b2.y;
            o1.x = acc[i][j][2] + b2.x; o1.y = acc[i][j][3] + b2.y;
            *(float2*)(C + (size_t)m * D_ + n) = o0;
            *(float2*)(C + (size_t)(m + 8) * D_ + n) = o1;
        }
    }
}

// ---------------------------------------------------------------------------
// HMMA flash attention: kv tile 128, K/V hi-only, Q fp16 hi/lo,
// P hi-only. ctx written hi-only. 1 CTA/SM. (unchanged from R14)
// ---------------------------------------------------------------------------
#define FROWB 144
#define KARRB (128 * FROWB)              // 18432
#define FSTGB (2 * KARRB)                // 36864
#define FAH_SMEM (2 * FSTGB)             // 73728

__device__ __forceinline__ void fa_stage_load(
    uint32_t stb, size_t base, int k0, int tid,
    const __half* __restrict__ Khi, const __half* __restrict__ Vhi)
{
    const int arr = tid >> 7, row = tid & 127;
    const __half* src = (arr == 0) ? Khi : Vhi;
    const __half* p = src + base + (size_t)(k0 + row) * D_;
    const uint32_t d = stb + arr * KARRB + row * FROWB;
    #pragma unroll
    for (int seg = 0; seg < 8; seg++)
        cp16(d + seg * 16, p + seg * 8);
}

#define LOADK(ks_, jg_, p_) do {                                               \
    _Pragma("unroll")                                                          \
    for (int t2 = 0; t2 < 4; t2++) {                                           \
        const uint32_t ba = stb + kb4                                          \
            + (uint32_t)(((jg_) + 2 * t2) * 8 * FROWB + (ks_) * 32);           \
        uint32_t rr[4];                                                        \
        ldsm4(rr, ba);                                                         \
        kh2[p_][2*t2][0] = rr[0]; kh2[p_][2*t2][1] = rr[1];                    \
        kh2[p_][2*t2+1][0] = rr[2]; kh2[p_][2*t2+1][1] = rr[3];                \
    }                                                                          \
} while (0)

#define LOADV(ks_, p_) do {                                                    \
    _Pragma("unroll")                                                          \
    for (int t2 = 0; t2 < 4; t2++) {                                           \
        const uint32_t va = stb + KARRB + vb4                                  \
            + (uint32_t)((ks_) * 16 * FROWB + 2 * t2 * 16);                    \
        uint32_t rr[4];                                                        \
        ldsm4t(rr, va);                                                        \
        vh2[p_][2*t2][0] = rr[0]; vh2[p_][2*t2][1] = rr[1];                    \
        vh2[p_][2*t2+1][0] = rr[2]; vh2[p_][2*t2+1][1] = rr[3];                \
    }                                                                          \
} while (0)

#define PCVT(ks_, p_) do {                                                     \
    pah2[p_][0] = pack16(sacc[2*(ks_)][0],   sacc[2*(ks_)][1]);                \
    pah2[p_][1] = pack16(sacc[2*(ks_)][2],   sacc[2*(ks_)][3]);                \
    pah2[p_][2] = pack16(sacc[2*(ks_)+1][0], sacc[2*(ks_)+1][1]);              \
    pah2[p_][3] = pack16(sacc[2*(ks_)+1][2], sacc[2*(ks_)+1][3]);              \
} while (0)

__global__ void __launch_bounds__(256, 1)
flash_hmma(const __half* __restrict__ Qhi, const __half* __restrict__ Qlo,
           const __half* __restrict__ Khi, const __half* __restrict__ Vhi,
           __half* __restrict__ chi)
{
    extern __shared__ uint32_t su[];
    const uint32_t sb = smem_u32(su);
    char* sc = (char*)su;

    const int tid = threadIdx.x, wid = tid >> 5, lid = tid & 31;
    const int g = lid >> 2, tc = lid & 3;
    const int bh = blockIdx.y;
    const int bx = (int)gridDim.x - 1 - (int)blockIdx.x;   // heavy tiles first
    const int b = bh / H_, h = bh % H_;
    const int q0 = bx * 128;
    const size_t base = (size_t)b * S_ * D_ + (size_t)h * DH_;
    const int wrow = q0 + wid * 16;
    const int ktiles = bx + 1;

    fa_stage_load(sb, base, 0, tid, Khi, Vhi);
    cp_commit();

    // stage Q through buffer 1 (Qhi at +0, Qlo at +KARRB)
    #pragma unroll
    for (int it = 0; it < 4; it++) {
        const int idx = tid + it * 256;
        const int row = idx >> 3, seg = idx & 7;
        const size_t e = base + (size_t)(q0 + row) * D_ + seg * 8;
        *(uint4*)(sc + FSTGB + row * FROWB + seg * 16)         = *(const uint4*)(Qhi + e);
        *(uint4*)(sc + FSTGB + KARRB + row * FROWB + seg * 16) = *(const uint4*)(Qlo + e);
    }
    __syncthreads();

    uint32_t qh[4][4], ql[4][4];
    {
        const uint32_t aa0 = sb + FSTGB
                           + (uint32_t)((wid * 16 + (lid & 15)) * FROWB + (lid >> 4) * 16);
        #pragma unroll
        for (int ks = 0; ks < 4; ks++) {
            ldsm4(qh[ks], aa0 + ks * 32);
            ldsm4(ql[ks], aa0 + KARRB + ks * 32);
        }
    }

    float oacc[8][4];
    #pragma unroll
    for (int j = 0; j < 8; j++)
        #pragma unroll
        for (int q = 0; q < 4; q++) oacc[j][q] = 0.0f;
    float m0r = -1e30f, m1r = -1e30f, l0r = 0.0f, l1r = 0.0f;

    const uint32_t kb4 = (uint32_t)(((lid & 7) + ((lid >> 4) << 3)) * FROWB
                                    + ((lid >> 3) & 1) * 16);
    const uint32_t vb4 = (uint32_t)((lid & 15) * FROWB + ((lid >> 4) & 1) * 16);

    for (int kt = 0; kt < ktiles; kt++) {
        const int k0 = kt * 128;
        cp_wait_all();
        __syncthreads();
        if (kt + 1 < ktiles) {
            fa_stage_load(sb + ((kt + 1) & 1) * FSTGB, base, k0 + 128, tid, Khi, Vhi);
            cp_commit();
        }

        const uint32_t stb = sb + (kt & 1) * FSTGB;

        // ---- S = Q @ K^T (2 MMAs per acc) ----
        float sacc[16][4];
        #pragma unroll
        for (int j = 0; j < 16; j++)
            #pragma unroll
            for (int q = 0; q < 4; q++) sacc[j][q] = 0.0f;

        {
            uint32_t kh2[2][8][2];
            LOADK(0, 0, 0);
            #pragma unroll
            for (int st = 0; st < 8; st++) {
                const int ks = st >> 1, jg = (st & 1) * 8, p = st & 1;
                if (st < 7) {
                    const int ks2 = (st + 1) >> 1, jg2 = ((st + 1) & 1) * 8;
                    LOADK(ks2, jg2, p ^ 1);
                }
                #pragma unroll
                for (int t = 0; t < 8; t++) mma16816(sacc[jg + t], qh[ks], kh2[p][t]);
                #pragma unroll
                for (int t = 0; t < 8; t++) mma16816(sacc[jg + t], ql[ks], kh2[p][t]);
            }
        }

        // ---- causal mask (diagonal tile only) ----
        if (k0 + 127 > wrow) {
            #pragma unroll
            for (int jn = 0; jn < 16; jn++) {
                const int c0 = k0 + jn * 8 + 2 * tc;
                const int r0g = wrow + g;
                if (c0     > r0g)     sacc[jn][0] = -1e30f;
                if (c0 + 1 > r0g)     sacc[jn][1] = -1e30f;
                if (c0     > r0g + 8) sacc[jn][2] = -1e30f;
                if (c0 + 1 > r0g + 8) sacc[jn][3] = -1e30f;
            }
        }

        // ---- online softmax (ex2) ----
        float mt0 = -1e30f, mt1 = -1e30f;
        #pragma unroll
        for (int jn = 0; jn < 16; jn += 2) {
            float u = fmaxf(fmaxf(sacc[jn][0], sacc[jn][1]),
                            fmaxf(sacc[jn+1][0], sacc[jn+1][1]));
            float v = fmaxf(fmaxf(sacc[jn][2], sacc[jn][3]),
                            fmaxf(sacc[jn+1][2], sacc[jn+1][3]));
            mt0 = fmaxf(mt0, u);
            mt1 = fmaxf(mt1, v);
        }
        mt0 = fmaxf(mt0, __shfl_xor_sync(0xffffffffu, mt0, 1));
        mt0 = fmaxf(mt0, __shfl_xor_sync(0xffffffffu, mt0, 2));
        mt1 = fmaxf(mt1, __shfl_xor_sync(0xffffffffu, mt1, 1));
        mt1 = fmaxf(mt1, __shfl_xor_sync(0xffffffffu, mt1, 2));

        const float mn0 = fmaxf(m0r, mt0), mn1 = fmaxf(m1r, mt1);
        const float al0 = ex2f(m0r - mn0), al1 = ex2f(m1r - mn1);
        m0r = mn0; m1r = mn1;

        #pragma unroll
        for (int jn = 0; jn < 16; jn++) {
            sacc[jn][0] = ex2f(sacc[jn][0] - mn0);
            sacc[jn][1] = ex2f(sacc[jn][1] - mn0);
            sacc[jn][2] = ex2f(sacc[jn][2] - mn1);
            sacc[jn][3] = ex2f(sacc[jn][3] - mn1);
        }
        float p0 = 0.0f, p1 = 0.0f, p2 = 0.0f, p3 = 0.0f;
        #pragma unroll
        for (int jn = 0; jn < 16; jn += 2) {
            p0 += sacc[jn][0] + sacc[jn][1];
            p1 += sacc[jn+1][0] + sacc[jn+1][1];
            p2 += sacc[jn][2] + sacc[jn][3];
            p3 += sacc[jn+1][2] + sacc[jn+1][3];
        }
        float ls0 = p0 + p1, ls1 = p2 + p3;
        ls0 += __shfl_xor_sync(0xffffffffu, ls0, 1);
        ls0 += __shfl_xor_sync(0xffffffffu, ls0, 2);
        ls1 += __shfl_xor_sync(0xffffffffu, ls1, 1);
        ls1 += __shfl_xor_sync(0xffffffffu, ls1, 2);
        l0r = l0r * al0 + ls0;
        l1r = l1r * al1 + ls1;

        #pragma unroll
        for (int jn = 0; jn < 8; jn++) {
            oacc[jn][0] *= al0; oacc[jn][1] *= al0;
            oacc[jn][2] *= al1; oacc[jn][3] *= al1;
        }

        // ---- O += P @ V (P hi-only: 1 MMA per acc; V+P double-buffered) ----
        {
            uint32_t vh2[2][8][2];
            uint32_t pah2[2][4];
            LOADV(0, 0);
            PCVT(0, 0);
            #pragma unroll
            for (int ks = 0; ks < 8; ks++) {
                const int p = ks & 1;
                if (ks < 7) {
                    LOADV(ks + 1, p ^ 1);
                    PCVT(ks + 1, p ^ 1);
                }
                #pragma unroll
                for (int t = 0; t < 8; t++) mma16816(oacc[t], pah2[p], vh2[p][t]);
            }
        }
    }

    // normalize + store ctx hi-only fp16
    const float inv0 = 1.0f / l0r, inv1 = 1.0f / l1r;
    const int row0 = q0 + wid * 16 + g;
    #pragma unroll
    for (int jn = 0; jn < 8; jn++) {
        const int c = jn * 8 + 2 * tc;
        *(uint32_t*)(chi + base + (size_t)row0 * D_ + c) =
            pack16(oacc[jn][0] * inv0, oacc[jn][1] * inv0);
        *(uint32_t*)(chi + base + (size_t)(row0 + 8) * D_ + c) =
            pack16(oacc[jn][2] * inv1, oacc[jn][3] * inv1);
    }
}

// ---------------------------------------------------------------------------
// Launch
// ---------------------------------------------------------------------------
extern "C" void kernel_launch(void* const* d_in, const int* in_sizes, int n_in,
                              void* d_out, int out_size)
{
    const float* query = (const float*)d_in[0];
    const float* key   = (const float*)d_in[1];
    const float* value = (const float*)d_in[2];
    const float* Wq    = (const float*)d_in[4];
    const float* bq    = (const float*)d_in[5];
    const float* Wk    = (const float*)d_in[6];
    const float* bk    = (const float*)d_in[7];
    const float* Wv    = (const float*)d_in[8];
    const float* bv    = (const float*)d_in[9];
    const float* Wo    = (const float*)d_in[10];
    const float* bo    = (const float*)d_in[11];
    float* out = (float*)d_out;

    __half *inhi, *qkvhi, *qkvlo, *chi, *whi;
    cudaGetSymbolAddress((void**)&inhi, g_inhi);
    cudaGetSymbolAddress((void**)&qkvhi, g_qkvhi);
    cudaGetSymbolAddress((void**)&qkvlo, g_qkvlo);
    cudaGetSymbolAddress((void**)&chi, g_chi);
    cudaGetSymbolAddress((void**)&whi, g_whi);

    cudaFuncSetAttribute(gemm_qkv, cudaFuncAttributeMaxDynamicSharedMemorySize, GEMM_SMEM);
    cudaFuncSetAttribute(gemm_o,   cudaFuncAttributeMaxDynamicSharedMemorySize, GEMM_SMEM);
    cudaFuncSetAttribute(flash_hmma, cudaFuncAttributeMaxDynamicSharedMemorySize, FAH_SMEM);

    prep_w<<<dim3(32, 32, 4), dim3(32, 8)>>>(Wq, Wk, Wv, Wo, whi);
    prep_in<<<dim3(MROWS * D_ / 4 / 256, 3), 256>>>(query, key, value, inhi);

    gemm_qkv<<<dim3(D_ / 128, MROWS / 128, 3), 256, GEMM_SMEM>>>(
        inhi, whi, bq, bk, bv, qkvhi, qkvlo);

    flash_hmma<<<dim3(S_ / 128, B_ * H_), 256, FAH_SMEM>>>(
        qkvhi, qkvlo,
        qkvhi + ISZ,
        qkvhi + 2 * ISZ,
        chi);

    gemm_o<<<dim3(D_ / 128, MROWS / 128), 256, GEMM_SMEM>>>(
        chi, whi + 3 * WSZ, bo, out);
}